// round 4
// baseline (speedup 1.0000x reference)
#include <cuda_runtime.h>

// Fused MHA: B=2, N=2048, C=1152, H=16, HD=72
// Round-2 baseline: fp32 SIMT, 3 kernels (QKV GEMM -> flash attention -> proj GEMM).
// Scratch lives in __device__ globals (allocation-free, graph-capturable).

#define B_   2
#define N_   2048
#define C_   1152
#define H_   16
#define HD_  72
#define HD2_ 80          // padded head dim for alignment
#define NEG_ (-100000000.0f)
#define SCALE_ 0.11785113019775793f   // 72^-0.5

// Scratch: Q/K/V in [B][H][N][HD2] layout (Q pre-scaled), attention output [B][N][C]
__device__ float g_q[B_*H_*N_*HD2_];
__device__ float g_k[B_*H_*N_*HD2_];
__device__ float g_v[B_*H_*N_*HD2_];
__device__ float g_ao[B_*N_*C_];

// ---------------------------------------------------------------------------
// Kernel 1: QKV GEMM.  out[m, j] = dot(x[m, :], w_qkv[j, :])   (NT gemm)
// M=4096 (b,n), Nj=3456 (3*C), K=1152.  128x128 block tile, BK=16, 8x8/thread.
// Epilogue scatters into g_q/g_k/g_v with head split; Q scaled by SCALE_.
// ---------------------------------------------------------------------------
__global__ __launch_bounds__(256) void qkv_kernel(const float* __restrict__ x,
                                                  const float* __restrict__ w) {
    __shared__ float As[16][132];   // transposed [k][m], pad 132 (528B rows, 16B aligned)
    __shared__ float Bs[16][132];   // transposed [k][n]
    const int t  = threadIdx.x;
    const int lr = t >> 2, ls = t & 3;       // loader: row 0..63, 16B segment 0..3
    const int ty = t >> 4, tx = t & 15;      // compute: 16x16 grid of 8x8 tiles
    const float* Ab = x + (size_t)blockIdx.y * 128 * C_;
    const float* Bb = w + (size_t)blockIdx.x * 128 * C_;
    float acc[8][8] = {};

    for (int k0 = 0; k0 < C_; k0 += 16) {
        float4 a0 = *(const float4*)(Ab + lr * C_        + k0 + ls * 4);
        float4 a1 = *(const float4*)(Ab + (lr + 64) * C_ + k0 + ls * 4);
        float4 b0 = *(const float4*)(Bb + lr * C_        + k0 + ls * 4);
        float4 b1 = *(const float4*)(Bb + (lr + 64) * C_ + k0 + ls * 4);
        __syncthreads();
        As[ls*4+0][lr]    = a0.x; As[ls*4+1][lr]    = a0.y; As[ls*4+2][lr]    = a0.z; As[ls*4+3][lr]    = a0.w;
        As[ls*4+0][lr+64] = a1.x; As[ls*4+1][lr+64] = a1.y; As[ls*4+2][lr+64] = a1.z; As[ls*4+3][lr+64] = a1.w;
        Bs[ls*4+0][lr]    = b0.x; Bs[ls*4+1][lr]    = b0.y; Bs[ls*4+2][lr]    = b0.z; Bs[ls*4+3][lr]    = b0.w;
        Bs[ls*4+0][lr+64] = b1.x; Bs[ls*4+1][lr+64] = b1.y; Bs[ls*4+2][lr+64] = b1.z; Bs[ls*4+3][lr+64] = b1.w;
        __syncthreads();
        #pragma unroll
        for (int kk = 0; kk < 16; kk++) {
            float a[8], b[8];
            *(float4*)(a)     = *(const float4*)&As[kk][ty*8];
            *(float4*)(a + 4) = *(const float4*)&As[kk][ty*8 + 4];
            *(float4*)(b)     = *(const float4*)&Bs[kk][tx*8];
            *(float4*)(b + 4) = *(const float4*)&Bs[kk][tx*8 + 4];
            #pragma unroll
            for (int i = 0; i < 8; i++)
                #pragma unroll
                for (int j = 0; j < 8; j++)
                    acc[i][j] += a[i] * b[j];
        }
    }

    // Epilogue: scatter. Tile width 128 never crosses the q/k/v boundary (1152 = 9*128).
    const int part = (blockIdx.x * 128) / C_;        // 0=q 1=k 2=v
    float* dst = (part == 0) ? g_q : ((part == 1) ? g_k : g_v);
    const float sc = (part == 0) ? SCALE_ : 1.0f;    // pre-scale Q
    int hj[8], dj[8];
    #pragma unroll
    for (int j = 0; j < 8; j++) {
        int jj = blockIdx.x * 128 + tx * 8 + j - part * C_;
        hj[j] = jj / HD_;
        dj[j] = jj - hj[j] * HD_;
    }
    #pragma unroll
    for (int i = 0; i < 8; i++) {
        int m  = blockIdx.y * 128 + ty * 8 + i;
        int bb = m >> 11;            // / N_
        int n  = m & (N_ - 1);
        #pragma unroll
        for (int j = 0; j < 8; j++)
            dst[((bb * H_ + hj[j]) * N_ + n) * HD2_ + dj[j]] = acc[i][j] * sc;
    }
}

// ---------------------------------------------------------------------------
// Kernel 2: flash attention. One block = 64 q rows of one (b, h).
// 256 threads. Dynamic smem 78336 B (2 CTAs/SM).
// Online softmax with per-row (m, l) in smem; O accum in registers (4 rows x 5 cols).
// Logits computed as dot + bias in fp32 -> reproduces the reference's -1e8
// absorption (fully-masked rows become uniform attention), so no NaN path.
// ---------------------------------------------------------------------------
__global__ __launch_bounds__(256, 2) void attn_kernel(const int* __restrict__ mask) {
    extern __shared__ float sm[];
    float* Qt   = sm;              // [72][68]  transposed (d-major), pre-scaled
    float* Kt   = sm + 4896;       // [72][68]  transposed
    float* S    = sm + 9792;       // [64][68]  scores -> probabilities
    float* Vs   = sm + 14144;      // [64][80]  row-major, cols 72..79 zeroed
    float* m_s  = sm + 19264;      // [64] running max
    float* l_s  = sm + 19328;      // [64] running sum
    float* al_s = sm + 19392;      // [64] rescale factor
    int*   mqi  = (int*)(sm + 19456);  // [64] query mask
    int*   mki  = (int*)(sm + 19520);  // [64] key mask (per tile)

    const int t  = threadIdx.x;
    const int qt = blockIdx.x;     // q tile 0..31
    const int h  = blockIdx.y;
    const int b  = blockIdx.z;
    const float* qp = g_q + ((b * H_ + h) * N_ + qt * 64) * HD2_;
    const float* kp = g_k + (b * H_ + h) * N_ * HD2_;
    const float* vp = g_v + (b * H_ + h) * N_ * HD2_;

    const int lr = t >> 2, rem = t & 3;     // loaders
    const int ty = t >> 4, tx = t & 15;
    const int r0 = ty * 4;                  // 4 q-rows per thread
    const int c0 = tx * 5;                  // 5 output cols per thread (HD2=80)

    // Load Q tile transposed (already scaled in kernel 1)
    for (int s = rem; s < 18; s += 4) {
        float4 v = *(const float4*)(qp + lr * HD2_ + s * 4);
        Qt[(s*4+0)*68 + lr] = v.x;
        Qt[(s*4+1)*68 + lr] = v.y;
        Qt[(s*4+2)*68 + lr] = v.z;
        Qt[(s*4+3)*68 + lr] = v.w;
    }
    if (t < 64) {
        mqi[t] = mask[b * N_ + qt * 64 + t];
        m_s[t] = -3.0e38f;
        l_s[t] = 0.0f;
    }
    float O[4][5] = {};
    __syncthreads();

    for (int kt = 0; kt < 32; kt++) {
        // ---- load K (transposed) + V tiles + key mask ----
        for (int s = rem; s < 18; s += 4) {
            float4 kv = *(const float4*)(kp + (kt * 64 + lr) * HD2_ + s * 4);
            Kt[(s*4+0)*68 + lr] = kv.x;
            Kt[(s*4+1)*68 + lr] = kv.y;
            Kt[(s*4+2)*68 + lr] = kv.z;
            Kt[(s*4+3)*68 + lr] = kv.w;
            float4 vv = *(const float4*)(vp + (kt * 64 + lr) * HD2_ + s * 4);
            *(float4*)&Vs[lr * HD2_ + s * 4] = vv;
        }
        if (t < 128) {   // zero V pad cols 72..79
            int row = t >> 1;
            float4 z = make_float4(0.f, 0.f, 0.f, 0.f);
            *(float4*)&Vs[row * HD2_ + 72 + (t & 1) * 4] = z;
        }
        if (t < 64) mki[t] = mask[b * N_ + kt * 64 + t];
        __syncthreads();

        // ---- S = Q K^T  (already scaled) + bias ----
        {
            float acc[4][4] = {};
            #pragma unroll 8
            for (int d = 0; d < HD_; d++) {
                float a[4], bb4[4];
                *(float4*)a   = *(const float4*)&Qt[d * 68 + r0];
                *(float4*)bb4 = *(const float4*)&Kt[d * 68 + tx * 4];
                #pragma unroll
                for (int i = 0; i < 4; i++)
                    #pragma unroll
                    for (int j = 0; j < 4; j++)
                        acc[i][j] += a[i] * bb4[j];
            }
            #pragma unroll
            for (int i = 0; i < 4; i++) {
                int mq = mqi[r0 + i];
                #pragma unroll
                for (int j = 0; j < 4; j++) {
                    int c = tx * 4 + j;
                    float bias = (mq && mki[c]) ? 0.0f : NEG_;
                    S[(r0 + i) * 68 + c] = acc[i][j] + bias;
                }
            }
        }
        __syncthreads();

        // ---- online softmax row update (one thread per row) ----
        if (t < 64) {
            float* Sr = S + t * 68;
            float mold = m_s[t];
            float mx = mold;
            #pragma unroll 8
            for (int c = 0; c < 64; c++) mx = fmaxf(mx, Sr[c]);
            float al = __expf(mold - mx);     // 0 on first tile (mold = -3e38)
            float sum = 0.0f;
            #pragma unroll 8
            for (int c = 0; c < 64; c++) {
                float p = __expf(Sr[c] - mx);
                Sr[c] = p;
                sum += p;
            }
            l_s[t]  = l_s[t] * al + sum;
            m_s[t]  = mx;
            al_s[t] = al;
        }
        __syncthreads();

        // ---- O = O*alpha + P @ V ----
        {
            float al0 = al_s[r0], al1 = al_s[r0+1], al2 = al_s[r0+2], al3 = al_s[r0+3];
            #pragma unroll
            for (int j = 0; j < 5; j++) {
                O[0][j] *= al0; O[1][j] *= al1; O[2][j] *= al2; O[3][j] *= al3;
            }
            #pragma unroll 4
            for (int kk4 = 0; kk4 < 16; kk4++) {
                float sa[4][4];
                #pragma unroll
                for (int i = 0; i < 4; i++)
                    *(float4*)sa[i] = *(const float4*)&S[(r0 + i) * 68 + kk4 * 4];
                #pragma unroll
                for (int jj = 0; jj < 4; jj++) {
                    const float* vrow = &Vs[(kk4 * 4 + jj) * HD2_ + c0];
                    float v0 = vrow[0], v1 = vrow[1], v2 = vrow[2], v3 = vrow[3], v4 = vrow[4];
                    #pragma unroll
                    for (int i = 0; i < 4; i++) {
                        float p = sa[i][jj];
                        O[i][0] += p * v0; O[i][1] += p * v1; O[i][2] += p * v2;
                        O[i][3] += p * v3; O[i][4] += p * v4;
                    }
                }
            }
        }
        __syncthreads();
    }

    // ---- finalize: divide by l, store [b, n, h*HD + d] ----
    #pragma unroll
    for (int i = 0; i < 4; i++) {
        int r = r0 + i;
        float inv = 1.0f / l_s[r];        // l >= 1 always
        int n = qt * 64 + r;
        float* op = g_ao + (b * N_ + n) * C_ + h * HD_;
        #pragma unroll
        for (int j = 0; j < 5; j++) {
            int c = c0 + j;
            if (c < HD_) op[c] = O[i][j] * inv;
        }
    }
}

// ---------------------------------------------------------------------------
// Kernel 3: output projection.  out[m, j] = dot(ao[m, :], w_proj[j, :]) + b[j]
// M=4096, Nj=1152, K=1152. Same 128x128x16 NT GEMM.
// ---------------------------------------------------------------------------
__global__ __launch_bounds__(256) void proj_kernel(const float* __restrict__ w,
                                                   const float* __restrict__ bias,
                                                   float* __restrict__ out) {
    __shared__ float As[16][132];
    __shared__ float Bs[16][132];
    const int t  = threadIdx.x;
    const int lr = t >> 2, ls = t & 3;
    const int ty = t >> 4, tx = t & 15;
    const float* Ab = g_ao + (size_t)blockIdx.y * 128 * C_;
    const float* Bb = w    + (size_t)blockIdx.x * 128 * C_;
    float acc[8][8] = {};

    for (int k0 = 0; k0 < C_; k0 += 16) {
        float4 a0 = *(const float4*)(Ab + lr * C_        + k0 + ls * 4);
        float4 a1 = *(const float4*)(Ab + (lr + 64) * C_ + k0 + ls * 4);
        float4 b0 = *(const float4*)(Bb + lr * C_        + k0 + ls * 4);
        float4 b1 = *(const float4*)(Bb + (lr + 64) * C_ + k0 + ls * 4);
        __syncthreads();
        As[ls*4+0][lr]    = a0.x; As[ls*4+1][lr]    = a0.y; As[ls*4+2][lr]    = a0.z; As[ls*4+3][lr]    = a0.w;
        As[ls*4+0][lr+64] = a1.x; As[ls*4+1][lr+64] = a1.y; As[ls*4+2][lr+64] = a1.z; As[ls*4+3][lr+64] = a1.w;
        Bs[ls*4+0][lr]    = b0.x; Bs[ls*4+1][lr]    = b0.y; Bs[ls*4+2][lr]    = b0.z; Bs[ls*4+3][lr]    = b0.w;
        Bs[ls*4+0][lr+64] = b1.x; Bs[ls*4+1][lr+64] = b1.y; Bs[ls*4+2][lr+64] = b1.z; Bs[ls*4+3][lr+64] = b1.w;
        __syncthreads();
        #pragma unroll
        for (int kk = 0; kk < 16; kk++) {
            float a[8], b[8];
            *(float4*)(a)     = *(const float4*)&As[kk][ty*8];
            *(float4*)(a + 4) = *(const float4*)&As[kk][ty*8 + 4];
            *(float4*)(b)     = *(const float4*)&Bs[kk][tx*8];
            *(float4*)(b + 4) = *(const float4*)&Bs[kk][tx*8 + 4];
            #pragma unroll
            for (int i = 0; i < 8; i++)
                #pragma unroll
                for (int j = 0; j < 8; j++)
                    acc[i][j] += a[i] * b[j];
        }
    }

    #pragma unroll
    for (int i = 0; i < 8; i++) {
        int m = blockIdx.y * 128 + ty * 8 + i;
        #pragma unroll
        for (int j = 0; j < 8; j++) {
            int jj = blockIdx.x * 128 + tx * 8 + j;
            out[(size_t)m * C_ + jj] = acc[i][j] + bias[jj];
        }
    }
}

// ---------------------------------------------------------------------------
extern "C" void kernel_launch(void* const* d_in, const int* in_sizes, int n_in,
                              void* d_out, int out_size) {
    const float* x      = (const float*)d_in[0];
    const int*   amask  = (const int*)  d_in[1];
    const float* w_qkv  = (const float*)d_in[2];
    const float* w_proj = (const float*)d_in[3];
    const float* b_proj = (const float*)d_in[4];
    float* out = (float*)d_out;

    cudaFuncSetAttribute(attn_kernel, cudaFuncAttributeMaxDynamicSharedMemorySize, 78336);

    qkv_kernel<<<dim3(27, 32), 256>>>(x, w_qkv);                 // 3456/128 x 4096/128
    attn_kernel<<<dim3(32, 16, 2), 256, 78336>>>(amask);         // qtiles x H x B
    proj_kernel<<<dim3(9, 32), 256>>>(w_proj, b_proj, out);      // 1152/128 x 4096/128
}

// round 11
// speedup vs baseline: 2.3179x; 2.3179x over previous
#include <cuda_runtime.h>

// Fused MHA: B=2, N=2048, C=1152, H=16, HD=72
// tf32 tensor-core (mma.sync.m16n8k8) for all matmul stages.
// 3 kernels: QKV GEMM -> flash attention -> proj GEMM. Scratch in __device__
// globals (allocation-free, graph-capturable).
// Rounds 8-10 all failed PRE-LAUNCH on infra (device-busy x2, container
// acquisition failure x1). Design still unmeasured; resubmitting unchanged
// to keep the measurement unconfounded. 4th infra failure => escalate broker.

#define B_   2
#define N_   2048
#define C_   1152
#define H_   16
#define HD_  72
#define HD2_ 80
#define NEG_ (-100000000.0f)
#define SCALE_ 0.11785113019775793f   // 72^-0.5

// Q/K/V stored tf32-rounded (mma-ready), Q pre-scaled. [B][H][N][HD2]
__device__ float g_q[B_*H_*N_*HD2_];
__device__ float g_k[B_*H_*N_*HD2_];
__device__ float g_v[B_*H_*N_*HD2_];
__device__ float g_ao[B_*N_*C_];     // attention output, fp32

__device__ __forceinline__ float tf32r(float x) {
    unsigned u;
    asm("cvt.rna.tf32.f32 %0, %1;" : "=r"(u) : "f"(x));
    return __uint_as_float(u);
}

__device__ __forceinline__ void mma_tf32(float4& d, unsigned a0, unsigned a1,
                                         unsigned a2, unsigned a3,
                                         unsigned b0, unsigned b1) {
    asm volatile("mma.sync.aligned.m16n8k8.row.col.f32.tf32.tf32.f32 "
                 "{%0,%1,%2,%3},{%4,%5,%6,%7},{%8,%9},{%0,%1,%2,%3};"
                 : "+f"(d.x), "+f"(d.y), "+f"(d.z), "+f"(d.w)
                 : "r"(a0), "r"(a1), "r"(a2), "r"(a3), "r"(b0), "r"(b1));
}

// ---------------------------------------------------------------------------
// Kernel 1: QKV GEMM (NT).  M=4096, Nj=3456, K=1152.
// Block 128x128, BK=16, 8 warps (2M x 4N), warp tile 64x32 (4 m16 x 4 n8).
// Smem stride 20 -> conflict-free fragment gathers (r*20+c pattern).
// Epilogue scatters tf32-rounded values into g_q/g_k/g_v (Q pre-scaled).
// ---------------------------------------------------------------------------
__global__ __launch_bounds__(256, 2) void qkv_kernel(const float* __restrict__ x,
                                                     const float* __restrict__ w) {
    __shared__ float As[128 * 20];   // [m][k], stride 20
    __shared__ float Bs[128 * 20];   // [n][k], stride 20
    const unsigned* Asu = (const unsigned*)As;
    const unsigned* Bsu = (const unsigned*)Bs;
    const int t = threadIdx.x, l = t & 31, wid = t >> 5;
    const int wm = wid >> 2, wn = wid & 3;       // 2 x 4 warp grid
    const int r = l >> 2, c = l & 3;
    const int lrow = t >> 2, lseg = t & 3;       // loader mapping
    const float* Ab = x + (size_t)blockIdx.y * 128 * C_;
    const float* Bb = w + (size_t)blockIdx.x * 128 * C_;

    float4 acc[4][4];
    #pragma unroll
    for (int i = 0; i < 4; i++)
        #pragma unroll
        for (int j = 0; j < 4; j++) acc[i][j] = make_float4(0.f, 0.f, 0.f, 0.f);

    for (int k0 = 0; k0 < C_; k0 += 16) {
        float4 a0 = *(const float4*)(Ab + lrow * C_        + k0 + lseg * 4);
        float4 a1 = *(const float4*)(Ab + (lrow + 64) * C_ + k0 + lseg * 4);
        float4 b0 = *(const float4*)(Bb + lrow * C_        + k0 + lseg * 4);
        float4 b1 = *(const float4*)(Bb + (lrow + 64) * C_ + k0 + lseg * 4);
        __syncthreads();
        float4 ca;
        ca.x = tf32r(a0.x); ca.y = tf32r(a0.y); ca.z = tf32r(a0.z); ca.w = tf32r(a0.w);
        *(float4*)&As[lrow * 20 + lseg * 4] = ca;
        ca.x = tf32r(a1.x); ca.y = tf32r(a1.y); ca.z = tf32r(a1.z); ca.w = tf32r(a1.w);
        *(float4*)&As[(lrow + 64) * 20 + lseg * 4] = ca;
        ca.x = tf32r(b0.x); ca.y = tf32r(b0.y); ca.z = tf32r(b0.z); ca.w = tf32r(b0.w);
        *(float4*)&Bs[lrow * 20 + lseg * 4] = ca;
        ca.x = tf32r(b1.x); ca.y = tf32r(b1.y); ca.z = tf32r(b1.z); ca.w = tf32r(b1.w);
        *(float4*)&Bs[(lrow + 64) * 20 + lseg * 4] = ca;
        __syncthreads();

        #pragma unroll
        for (int ks = 0; ks < 2; ks++) {
            const int kb = ks * 8;
            unsigned af[4][4], bf[4][2];
            #pragma unroll
            for (int mt = 0; mt < 4; mt++) {
                int base = (wm * 64 + mt * 16 + r) * 20 + kb + c;
                af[mt][0] = Asu[base];
                af[mt][1] = Asu[base + 8 * 20];
                af[mt][2] = Asu[base + 4];
                af[mt][3] = Asu[base + 8 * 20 + 4];
            }
            #pragma unroll
            for (int nt = 0; nt < 4; nt++) {
                int nb = (wn * 32 + nt * 8 + r) * 20 + kb + c;
                bf[nt][0] = Bsu[nb];
                bf[nt][1] = Bsu[nb + 4];
            }
            #pragma unroll
            for (int mt = 0; mt < 4; mt++)
                #pragma unroll
                for (int nt = 0; nt < 4; nt++)
                    mma_tf32(acc[mt][nt], af[mt][0], af[mt][1], af[mt][2], af[mt][3],
                             bf[nt][0], bf[nt][1]);
        }
    }

    // Epilogue: tile width 128 never crosses q/k/v boundary (1152 = 9*128).
    const int part = (blockIdx.x * 128) / C_;
    float* dst = (part == 0) ? g_q : ((part == 1) ? g_k : g_v);
    const float sc = (part == 0) ? SCALE_ : 1.0f;
    #pragma unroll
    for (int mt = 0; mt < 4; mt++) {
        int m0 = blockIdx.y * 128 + wm * 64 + mt * 16 + r;
        #pragma unroll
        for (int nt = 0; nt < 4; nt++) {
            int col0 = blockIdx.x * 128 - part * C_ + wn * 32 + nt * 8 + c * 2;
            float v[4] = {acc[mt][nt].x, acc[mt][nt].y, acc[mt][nt].z, acc[mt][nt].w};
            #pragma unroll
            for (int e = 0; e < 4; e++) {
                int m  = m0 + (e >> 1) * 8;
                int jj = col0 + (e & 1);
                int hh = jj / HD_;
                int dd = jj - hh * HD_;
                int bb = m >> 11;            // / N_
                int nn = m & (N_ - 1);
                dst[((bb * H_ + hh) * N_ + nn) * HD2_ + dd] = tf32r(v[e] * sc);
            }
        }
    }
}

// ---------------------------------------------------------------------------
// Kernel 2: flash attention, tensor-core. One block = 64 q rows of one (b,h).
// 8 warps. KV tile 64. S phase: 4Mx2N warps (16x32 each). PV: 4Mx2N (16x40).
// Quad-shuffle softmax reductions; m/l update deferred to next iter's load
// phase -> 4 barriers per KV tile. Dynamic smem 83200 B (2 CTAs/SM).
// ---------------------------------------------------------------------------
__global__ __launch_bounds__(256, 2) void attn_kernel(const int* __restrict__ mask) {
    extern __shared__ float sm[];
    float* Qs   = sm;             // [64][76] tf32
    float* Ks   = sm + 4864;      // [64][76] tf32
    float* Vs   = sm + 9728;      // [64][88] tf32 (cols 72..79 zeros: g_v pad)
    float* Ps   = sm + 15360;     // [64][76] tf32 probabilities
    float* wmax = sm + 20224;     // [2][64] per-N-warp partial max
    float* wsum = sm + 20352;     // [2][64] per-N-warp partial sum
    float* m_s  = sm + 20480;     // [64] running max (lags one tile)
    float* l_s  = sm + 20544;     // [64] running sum (lags one tile)
    float* nm_s = sm + 20608;     // [64] current tile's new max
    int*   mqi  = (int*)(sm + 20672);
    int*   mki  = (int*)(sm + 20736);
    const unsigned* Qsu = (const unsigned*)Qs;
    const unsigned* Ksu = (const unsigned*)Ks;
    const unsigned* Vsu = (const unsigned*)Vs;
    const unsigned* Psu = (const unsigned*)Ps;

    const int t = threadIdx.x, l = t & 31, wid = t >> 5;
    const int r = l >> 2, c = l & 3;
    const int wm = wid >> 1, wn = wid & 1;    // 4M x 2N (both phases)
    const int qt = blockIdx.x, h = blockIdx.y, b = blockIdx.z;
    const float* qp = g_q + ((size_t)(b * H_ + h) * N_ + qt * 64) * HD2_;
    const float* kp = g_k + (size_t)(b * H_ + h) * N_ * HD2_;
    const float* vp = g_v + (size_t)(b * H_ + h) * N_ * HD2_;

    // Load Q tile (already scaled + tf32)
    for (int i = t; i < 64 * 18; i += 256) {
        int row = i / 18, s = i - row * 18;
        *(float4*)&Qs[row * 76 + s * 4] = *(const float4*)(qp + row * HD2_ + s * 4);
    }
    if (t < 64) { mqi[t] = mask[b * N_ + qt * 64 + t]; m_s[t] = -3.0e38f; l_s[t] = 0.f; }

    float4 O[5];
    #pragma unroll
    for (int nt = 0; nt < 5; nt++) O[nt] = make_float4(0.f, 0.f, 0.f, 0.f);

    const int lr0 = wm * 16 + r, lr1 = lr0 + 8;
    const int pc = wn * 40;

    for (int kt = 0; kt < 32; kt++) {
        __syncthreads();                       // B1: prev PV reads done
        if (t < 64 && kt > 0) {                // deferred m/l update (prev tile)
            float mo = m_s[t], nm = nm_s[t];
            l_s[t] = l_s[t] * __expf(mo - nm) + wsum[t] + wsum[64 + t];
            m_s[t] = nm;
        }
        for (int i = t; i < 64 * 20; i += 256) {
            int row = i / 20, s = i - row * 20;
            *(float4*)&Vs[row * 88 + s * 4] =
                *(const float4*)(vp + (size_t)(kt * 64 + row) * HD2_ + s * 4);
            if (s < 18)
                *(float4*)&Ks[row * 76 + s * 4] =
                    *(const float4*)(kp + (size_t)(kt * 64 + row) * HD2_ + s * 4);
        }
        if (t < 64) mki[t] = mask[b * N_ + kt * 64 + t];
        __syncthreads();                       // B2: tiles ready

        // ---- S = Q K^T (pre-scaled) ----
        float4 S4[4];
        #pragma unroll
        for (int nt = 0; nt < 4; nt++) S4[nt] = make_float4(0.f, 0.f, 0.f, 0.f);
        #pragma unroll
        for (int ks = 0; ks < 9; ks++) {
            const int kb = ks * 8;
            int ab = (wm * 16 + r) * 76 + kb + c;
            unsigned a0 = Qsu[ab], a1 = Qsu[ab + 8 * 76];
            unsigned a2 = Qsu[ab + 4], a3 = Qsu[ab + 8 * 76 + 4];
            #pragma unroll
            for (int nt = 0; nt < 4; nt++) {
                int nb = (wn * 32 + nt * 8 + r) * 76 + kb + c;
                mma_tf32(S4[nt], a0, a1, a2, a3, Ksu[nb], Ksu[nb + 4]);
            }
        }

        // ---- bias + tile row-max (quad shuffle + 2-warp smem exchange) ----
        const int mq0 = mqi[lr0], mq1 = mqi[lr1];
        float pm0 = -3.0e38f, pm1 = -3.0e38f;
        #pragma unroll
        for (int nt = 0; nt < 4; nt++) {
            int cc = wn * 32 + nt * 8 + c * 2;
            int mk0 = mki[cc], mk1 = mki[cc + 1];
            S4[nt].x += (mq0 && mk0) ? 0.f : NEG_;
            S4[nt].y += (mq0 && mk1) ? 0.f : NEG_;
            S4[nt].z += (mq1 && mk0) ? 0.f : NEG_;
            S4[nt].w += (mq1 && mk1) ? 0.f : NEG_;
            pm0 = fmaxf(pm0, fmaxf(S4[nt].x, S4[nt].y));
            pm1 = fmaxf(pm1, fmaxf(S4[nt].z, S4[nt].w));
        }
        pm0 = fmaxf(pm0, __shfl_xor_sync(0xffffffffu, pm0, 1));
        pm0 = fmaxf(pm0, __shfl_xor_sync(0xffffffffu, pm0, 2));
        pm1 = fmaxf(pm1, __shfl_xor_sync(0xffffffffu, pm1, 1));
        pm1 = fmaxf(pm1, __shfl_xor_sync(0xffffffffu, pm1, 2));
        if (c == 0) { wmax[wn * 64 + lr0] = pm0; wmax[wn * 64 + lr1] = pm1; }
        __syncthreads();                       // B3: wmax ready

        // ---- exp + P store + tile row-sum ----
        float nm0 = fmaxf(m_s[lr0], fmaxf(wmax[lr0], wmax[64 + lr0]));
        float nm1 = fmaxf(m_s[lr1], fmaxf(wmax[lr1], wmax[64 + lr1]));
        if (c == 0 && wn == 0) { nm_s[lr0] = nm0; nm_s[lr1] = nm1; }
        float ps0 = 0.f, ps1 = 0.f;
        #pragma unroll
        for (int nt = 0; nt < 4; nt++) {
            int cc = wn * 32 + nt * 8 + c * 2;
            float p00 = tf32r(__expf(S4[nt].x - nm0));
            float p01 = tf32r(__expf(S4[nt].y - nm0));
            float p10 = tf32r(__expf(S4[nt].z - nm1));
            float p11 = tf32r(__expf(S4[nt].w - nm1));
            ps0 += p00 + p01; ps1 += p10 + p11;
            *(float2*)&Ps[lr0 * 76 + cc] = make_float2(p00, p01);
            *(float2*)&Ps[lr1 * 76 + cc] = make_float2(p10, p11);
        }
        ps0 += __shfl_xor_sync(0xffffffffu, ps0, 1);
        ps0 += __shfl_xor_sync(0xffffffffu, ps0, 2);
        ps1 += __shfl_xor_sync(0xffffffffu, ps1, 1);
        ps1 += __shfl_xor_sync(0xffffffffu, ps1, 2);
        if (c == 0) { wsum[wn * 64 + lr0] = ps0; wsum[wn * 64 + lr1] = ps1; }
        __syncthreads();                       // B4: Ps + nm_s ready

        // ---- O = O*alpha + P @ V  (m_s still holds OLD max here) ----
        float al0 = __expf(m_s[lr0] - nm_s[lr0]);
        float al1 = __expf(m_s[lr1] - nm_s[lr1]);
        #pragma unroll
        for (int nt = 0; nt < 5; nt++) {
            O[nt].x *= al0; O[nt].y *= al0; O[nt].z *= al1; O[nt].w *= al1;
        }
        #pragma unroll
        for (int kk = 0; kk < 8; kk++) {
            const int kb = kk * 8;
            int ab = (wm * 16 + r) * 76 + kb + c;
            unsigned a0 = Psu[ab], a1 = Psu[ab + 8 * 76];
            unsigned a2 = Psu[ab + 4], a3 = Psu[ab + 8 * 76 + 4];
            #pragma unroll
            for (int nt = 0; nt < 5; nt++) {
                int vb = (kb + c) * 88 + pc + nt * 8 + r;
                mma_tf32(O[nt], a0, a1, a2, a3, Vsu[vb], Vsu[vb + 4 * 88]);
            }
        }
    }

    // final deferred l update
    __syncthreads();
    if (t < 64) {
        float mo = m_s[t], nm = nm_s[t];
        l_s[t] = l_s[t] * __expf(mo - nm) + wsum[t] + wsum[64 + t];
    }
    __syncthreads();

    // epilogue: divide by l, store [b, n, h*72 + d]
    float inv0 = 1.0f / l_s[lr0];
    float inv1 = 1.0f / l_s[lr1];
    float* op0 = g_ao + (size_t)(b * N_ + qt * 64 + lr0) * C_ + h * HD_;
    float* op1 = g_ao + (size_t)(b * N_ + qt * 64 + lr1) * C_ + h * HD_;
    #pragma unroll
    for (int nt = 0; nt < 5; nt++) {
        int d0 = pc + nt * 8 + c * 2;
        if (d0 < HD_) {
            op0[d0]     = O[nt].x * inv0;
            op0[d0 + 1] = O[nt].y * inv0;
            op1[d0]     = O[nt].z * inv1;
            op1[d0 + 1] = O[nt].w * inv1;
        }
    }
}

// ---------------------------------------------------------------------------
// Kernel 3: proj GEMM (NT) + bias.  M=4096, Nj=1152, K=1152. Same scheme.
// ---------------------------------------------------------------------------
__global__ __launch_bounds__(256, 2) void proj_kernel(const float* __restrict__ w,
                                                      const float* __restrict__ bias,
                                                      float* __restrict__ out) {
    __shared__ float As[128 * 20];
    __shared__ float Bs[128 * 20];
    const unsigned* Asu = (const unsigned*)As;
    const unsigned* Bsu = (const unsigned*)Bs;
    const int t = threadIdx.x, l = t & 31, wid = t >> 5;
    const int wm = wid >> 2, wn = wid & 3;
    const int r = l >> 2, c = l & 3;
    const int lrow = t >> 2, lseg = t & 3;
    const float* Ab = g_ao + (size_t)blockIdx.y * 128 * C_;
    const float* Bb = w    + (size_t)blockIdx.x * 128 * C_;

    float4 acc[4][4];
    #pragma unroll
    for (int i = 0; i < 4; i++)
        #pragma unroll
        for (int j = 0; j < 4; j++) acc[i][j] = make_float4(0.f, 0.f, 0.f, 0.f);

    for (int k0 = 0; k0 < C_; k0 += 16) {
        float4 a0 = *(const float4*)(Ab + lrow * C_        + k0 + lseg * 4);
        float4 a1 = *(const float4*)(Ab + (lrow + 64) * C_ + k0 + lseg * 4);
        float4 b0 = *(const float4*)(Bb + lrow * C_        + k0 + lseg * 4);
        float4 b1 = *(const float4*)(Bb + (lrow + 64) * C_ + k0 + lseg * 4);
        __syncthreads();
        float4 ca;
        ca.x = tf32r(a0.x); ca.y = tf32r(a0.y); ca.z = tf32r(a0.z); ca.w = tf32r(a0.w);
        *(float4*)&As[lrow * 20 + lseg * 4] = ca;
        ca.x = tf32r(a1.x); ca.y = tf32r(a1.y); ca.z = tf32r(a1.z); ca.w = tf32r(a1.w);
        *(float4*)&As[(lrow + 64) * 20 + lseg * 4] = ca;
        ca.x = tf32r(b0.x); ca.y = tf32r(b0.y); ca.z = tf32r(b0.z); ca.w = tf32r(b0.w);
        *(float4*)&Bs[lrow * 20 + lseg * 4] = ca;
        ca.x = tf32r(b1.x); ca.y = tf32r(b1.y); ca.z = tf32r(b1.z); ca.w = tf32r(b1.w);
        *(float4*)&Bs[(lrow + 64) * 20 + lseg * 4] = ca;
        __syncthreads();

        #pragma unroll
        for (int ks = 0; ks < 2; ks++) {
            const int kb = ks * 8;
            unsigned af[4][4], bf[4][2];
            #pragma unroll
            for (int mt = 0; mt < 4; mt++) {
                int base = (wm * 64 + mt * 16 + r) * 20 + kb + c;
                af[mt][0] = Asu[base];
                af[mt][1] = Asu[base + 8 * 20];
                af[mt][2] = Asu[base + 4];
                af[mt][3] = Asu[base + 8 * 20 + 4];
            }
            #pragma unroll
            for (int nt = 0; nt < 4; nt++) {
                int nb = (wn * 32 + nt * 8 + r) * 20 + kb + c;
                bf[nt][0] = Bsu[nb];
                bf[nt][1] = Bsu[nb + 4];
            }
            #pragma unroll
            for (int mt = 0; mt < 4; mt++)
                #pragma unroll
                for (int nt = 0; nt < 4; nt++)
                    mma_tf32(acc[mt][nt], af[mt][0], af[mt][1], af[mt][2], af[mt][3],
                             bf[nt][0], bf[nt][1]);
        }
    }

    #pragma unroll
    for (int mt = 0; mt < 4; mt++) {
        int m0 = blockIdx.y * 128 + wm * 64 + mt * 16 + r;
        #pragma unroll
        for (int nt = 0; nt < 4; nt++) {
            int col0 = blockIdx.x * 128 + wn * 32 + nt * 8 + c * 2;
            float bv0 = bias[col0], bv1 = bias[col0 + 1];
            out[(size_t)m0 * C_ + col0]           = acc[mt][nt].x + bv0;
            out[(size_t)m0 * C_ + col0 + 1]       = acc[mt][nt].y + bv1;
            out[(size_t)(m0 + 8) * C_ + col0]     = acc[mt][nt].z + bv0;
            out[(size_t)(m0 + 8) * C_ + col0 + 1] = acc[mt][nt].w + bv1;
        }
    }
}

// ---------------------------------------------------------------------------
extern "C" void kernel_launch(void* const* d_in, const int* in_sizes, int n_in,
                              void* d_out, int out_size) {
    const float* x      = (const float*)d_in[0];
    const int*   amask  = (const int*)  d_in[1];
    const float* w_qkv  = (const float*)d_in[2];
    const float* w_proj = (const float*)d_in[3];
    const float* b_proj = (const float*)d_in[4];
    float* out = (float*)d_out;

    cudaFuncSetAttribute(attn_kernel, cudaFuncAttributeMaxDynamicSharedMemorySize, 83200);

    qkv_kernel<<<dim3(27, 32), 256>>>(x, w_qkv);
    attn_kernel<<<dim3(32, 16, 2), 256, 83200>>>(amask);
    proj_kernel<<<dim3(9, 32), 256>>>(w_proj, b_proj, out);
}

// round 12
// speedup vs baseline: 2.9414x; 1.2690x over previous
#include <cuda_runtime.h>

// Fused MHA: B=2, N=2048, C=1152, H=16, HD=72
// Round-12: tf32 mma.m16n8k8 everywhere, with:
//  - k-slot pairing (slot c <-> real-k 2c, slot c+4 <-> real-k 2c+1) so all
//    fragments load as contiguous float2 (LDS.64), applied to A and B alike.
//  - attention: 128-row Q tile, warp-owns-16-rows -> warp-local softmax with
//    m/l in registers; P reused directly from S accumulators (no P smem);
//    V pre-transposed to [B][H][HD][N]; 2 barriers/tile.
//  - GEMMs: double-buffered smem, one barrier/iter, LDG overlapped.

#define B_   2
#define N_   2048
#define C_   1152
#define H_   16
#define HD_  72
#define HD2_ 80
#define NEG_ (-100000000.0f)
#define SCALE_ 0.11785113019775793f   // 72^-0.5

// Q/K tf32-rounded [B][H][N][HD2] (Q pre-scaled); V tf32 transposed [B][H][HD][N]
__device__ float g_q [B_*H_*N_*HD2_];
__device__ float g_k [B_*H_*N_*HD2_];
__device__ float g_vt[B_*H_*HD_*N_];
__device__ float g_ao[B_*N_*C_];

__device__ __forceinline__ float tf32r(float x) {
    unsigned u;
    asm("cvt.rna.tf32.f32 %0, %1;" : "=r"(u) : "f"(x));
    return __uint_as_float(u);
}

__device__ __forceinline__ void mma_tf32(float4& d, unsigned a0, unsigned a1,
                                         unsigned a2, unsigned a3,
                                         unsigned b0, unsigned b1) {
    asm volatile("mma.sync.aligned.m16n8k8.row.col.f32.tf32.tf32.f32 "
                 "{%0,%1,%2,%3},{%4,%5,%6,%7},{%8,%9},{%0,%1,%2,%3};"
                 : "+f"(d.x), "+f"(d.y), "+f"(d.z), "+f"(d.w)
                 : "r"(a0), "r"(a1), "r"(a2), "r"(a3), "r"(b0), "r"(b1));
}

#define F2U __float_as_uint

// Convert float4 to tf32 and store as float4
__device__ __forceinline__ void cvst(float* p, float4 v) {
    float4 cz;
    cz.x = tf32r(v.x); cz.y = tf32r(v.y); cz.z = tf32r(v.z); cz.w = tf32r(v.w);
    *(float4*)p = cz;
}

// ---------------------------------------------------------------------------
// Kernel 1: QKV GEMM (NT). M=4096, Nj=3456, K=1152. Block 128x128, BK=16,
// 8 warps (2M x 4N), warp 64x32. Double-buffered smem, stride 24.
// Fragments: A = 2x LDS.64, B = 1x LDS.64 (k-slot pairing).
// Epilogue: Q (scaled) / K to [B][H][N][80]; V transposed to [B][H][HD][N].
// ---------------------------------------------------------------------------
__global__ __launch_bounds__(256, 2) void qkv_kernel(const float* __restrict__ x,
                                                     const float* __restrict__ w) {
    __shared__ float As[2][128 * 24];
    __shared__ float Bs[2][128 * 24];
    const int t = threadIdx.x, l = t & 31, wid = t >> 5;
    const int wm = wid >> 2, wn = wid & 3;
    const int r = l >> 2, c = l & 3;
    const int lrow = t >> 2, lseg = t & 3;
    const float* Ab = x + (size_t)blockIdx.y * 128 * C_ + lrow * C_ + lseg * 4;
    const float* Bb = w + (size_t)blockIdx.x * 128 * C_ + lrow * C_ + lseg * 4;

    float4 acc[4][4];
    #pragma unroll
    for (int i = 0; i < 4; i++)
        #pragma unroll
        for (int j = 0; j < 4; j++) acc[i][j] = make_float4(0.f, 0.f, 0.f, 0.f);

    float4 ra0 = *(const float4*)(Ab);
    float4 ra1 = *(const float4*)(Ab + 64 * C_);
    float4 rb0 = *(const float4*)(Bb);
    float4 rb1 = *(const float4*)(Bb + 64 * C_);
    cvst(&As[0][lrow * 24 + lseg * 4], ra0);
    cvst(&As[0][(lrow + 64) * 24 + lseg * 4], ra1);
    cvst(&Bs[0][lrow * 24 + lseg * 4], rb0);
    cvst(&Bs[0][(lrow + 64) * 24 + lseg * 4], rb1);

    for (int k0 = 16; k0 <= C_; k0 += 16) {
        const int pb = ((k0 >> 4) + 1) & 1;    // buffer holding data for k0-16
        if (k0 < C_) {
            ra0 = *(const float4*)(Ab + k0);
            ra1 = *(const float4*)(Ab + 64 * C_ + k0);
            rb0 = *(const float4*)(Bb + k0);
            rb1 = *(const float4*)(Bb + 64 * C_ + k0);
        }
        __syncthreads();
        const float* Ap = As[pb];
        const float* Bp = Bs[pb];
        #pragma unroll
        for (int ks = 0; ks < 16; ks += 8) {
            unsigned a0[4], a1[4], a2[4], a3[4];
            #pragma unroll
            for (int mt = 0; mt < 4; mt++) {
                const float* q0 = Ap + (wm * 64 + mt * 16 + r) * 24 + ks + 2 * c;
                float2 la = *(const float2*)q0;
                float2 lb = *(const float2*)(q0 + 8 * 24);
                a0[mt] = F2U(la.x); a1[mt] = F2U(lb.x);
                a2[mt] = F2U(la.y); a3[mt] = F2U(lb.y);
            }
            #pragma unroll
            for (int nt = 0; nt < 4; nt++) {
                float2 bb = *(const float2*)(Bp + (wn * 32 + nt * 8 + r) * 24 + ks + 2 * c);
                unsigned b0 = F2U(bb.x), b1 = F2U(bb.y);
                #pragma unroll
                for (int mt = 0; mt < 4; mt++)
                    mma_tf32(acc[mt][nt], a0[mt], a1[mt], a2[mt], a3[mt], b0, b1);
            }
        }
        if (k0 < C_) {
            const int pn = pb ^ 1;
            cvst(&As[pn][lrow * 24 + lseg * 4], ra0);
            cvst(&As[pn][(lrow + 64) * 24 + lseg * 4], ra1);
            cvst(&Bs[pn][lrow * 24 + lseg * 4], rb0);
            cvst(&Bs[pn][(lrow + 64) * 24 + lseg * 4], rb1);
        }
    }

    // Epilogue: tile width 128 never crosses q/k/v boundary (1152 = 9*128).
    const int part = (blockIdx.x * 128) / C_;
    const float sc = (part == 0) ? SCALE_ : 1.0f;
    #pragma unroll
    for (int mt = 0; mt < 4; mt++) {
        int m0 = blockIdx.y * 128 + wm * 64 + mt * 16 + r;
        #pragma unroll
        for (int nt = 0; nt < 4; nt++) {
            int col0 = blockIdx.x * 128 - part * C_ + wn * 32 + nt * 8 + c * 2;
            float v[4] = {acc[mt][nt].x, acc[mt][nt].y, acc[mt][nt].z, acc[mt][nt].w};
            #pragma unroll
            for (int e = 0; e < 4; e++) {
                int m  = m0 + (e >> 1) * 8;
                int jj = col0 + (e & 1);
                int hh = jj / HD_;
                int dd = jj - hh * HD_;
                int bb = m >> 11;
                int nn = m & (N_ - 1);
                float val = tf32r(v[e] * sc);
                if (part == 0)
                    g_q[((size_t)(bb * H_ + hh) * N_ + nn) * HD2_ + dd] = val;
                else if (part == 1)
                    g_k[((size_t)(bb * H_ + hh) * N_ + nn) * HD2_ + dd] = val;
                else
                    g_vt[((size_t)(bb * H_ + hh) * HD_ + dd) * N_ + nn] = val;
            }
        }
    }
}

// ---------------------------------------------------------------------------
// Kernel 2: flash attention. One CTA = 128 q rows of one (b,h). 8 warps,
// warp w owns rows [w*16, w*16+16). KV tile 64. Per warp per tile:
// S (16x64) = 9ks x 8nt mma; softmax warp-local (quad shuffles, m/l regs);
// P = tf32(exp(S-m)) kept in the S accumulators and fed straight to PV as
// A-fragments (accumulator layout == A-operand layout under k-pairing).
// V read from g_vt (transposed) -> coalesced loads, float2 B-frags.
// 2 __syncthreads per tile. Dynamic smem 76,288 B -> 2 CTAs/SM.
// ---------------------------------------------------------------------------
__global__ __launch_bounds__(256, 2) void attn_kernel(const int* __restrict__ mask) {
    extern __shared__ float sm[];
    float* Qs = sm;                         // [128][72]
    float* Ks = sm + 128 * 72;              // [64][72]
    float* Vt = sm + 128 * 72 + 64 * 72;    // [72 hd][72] (cols 0..63 = seq k)
    int* mki = (int*)(sm + 128 * 72 + 64 * 72 + 72 * 72);   // [64]

    const int t = threadIdx.x, l = t & 31, wid = t >> 5;
    const int r = l >> 2, c = l & 3;
    const int qt = blockIdx.x, h = blockIdx.y, b = blockIdx.z;
    const int bh = b * H_ + h;
    const float* qp  = g_q  + ((size_t)bh * N_ + qt * 128) * HD2_;
    const float* kp  = g_k  + (size_t)bh * N_ * HD2_;
    const float* vtp = g_vt + (size_t)bh * HD_ * N_;

    // Q tile: 128 rows x 18 float4
    for (int i = t; i < 128 * 18; i += 256) {
        int row = i / 18, s = i - row * 18;
        *(float4*)&Qs[row * 72 + s * 4] = *(const float4*)(qp + row * HD2_ + s * 4);
    }
    const int q0 = qt * 128 + wid * 16;
    const int mq0 = mask[b * N_ + q0 + r];
    const int mq1 = mask[b * N_ + q0 + r + 8];

    float4 O[9];
    #pragma unroll
    for (int nt = 0; nt < 9; nt++) O[nt] = make_float4(0.f, 0.f, 0.f, 0.f);
    float m0 = -3.0e38f, m1 = -3.0e38f, l0 = 0.f, l1 = 0.f;

    const float* qrow0 = Qs + (wid * 16 + r) * 72 + 2 * c;
    const float* qrow1 = qrow0 + 8 * 72;

    for (int kt = 0; kt < 32; kt++) {
        __syncthreads();                    // prev tile's K/V reads complete
        for (int i = t; i < 64 * 18; i += 256) {
            int row = i / 18, s = i - row * 18;
            *(float4*)&Ks[row * 72 + s * 4] =
                *(const float4*)(kp + (size_t)(kt * 64 + row) * HD2_ + s * 4);
        }
        for (int i = t; i < 72 * 16; i += 256) {
            int row = i / 16, s = i - row * 16;
            *(float4*)&Vt[row * 72 + s * 4] =
                *(const float4*)(vtp + (size_t)row * N_ + kt * 64 + s * 4);
        }
        if (t < 64) mki[t] = mask[b * N_ + kt * 64 + t];
        __syncthreads();                    // tiles ready

        // ---- S = Q K^T (Q pre-scaled) ----
        float4 S4[8];
        #pragma unroll
        for (int nt = 0; nt < 8; nt++) S4[nt] = make_float4(0.f, 0.f, 0.f, 0.f);
        #pragma unroll
        for (int ks = 0; ks < 9; ks++) {
            const int kb = ks * 8;
            float2 la = *(const float2*)(qrow0 + kb);
            float2 lb = *(const float2*)(qrow1 + kb);
            unsigned a0 = F2U(la.x), a1 = F2U(lb.x), a2 = F2U(la.y), a3 = F2U(lb.y);
            #pragma unroll
            for (int nt = 0; nt < 8; nt++) {
                float2 bb = *(const float2*)(Ks + (nt * 8 + r) * 72 + kb + 2 * c);
                mma_tf32(S4[nt], a0, a1, a2, a3, F2U(bb.x), F2U(bb.y));
            }
        }

        // ---- bias + warp-local row max ----
        float pm0 = -3.0e38f, pm1 = -3.0e38f;
        #pragma unroll
        for (int nt = 0; nt < 8; nt++) {
            int cc = nt * 8 + 2 * c;
            int mk0 = mki[cc], mk1 = mki[cc + 1];
            S4[nt].x += (mq0 && mk0) ? 0.f : NEG_;
            S4[nt].y += (mq0 && mk1) ? 0.f : NEG_;
            S4[nt].z += (mq1 && mk0) ? 0.f : NEG_;
            S4[nt].w += (mq1 && mk1) ? 0.f : NEG_;
            pm0 = fmaxf(pm0, fmaxf(S4[nt].x, S4[nt].y));
            pm1 = fmaxf(pm1, fmaxf(S4[nt].z, S4[nt].w));
        }
        pm0 = fmaxf(pm0, __shfl_xor_sync(0xffffffffu, pm0, 1));
        pm0 = fmaxf(pm0, __shfl_xor_sync(0xffffffffu, pm0, 2));
        pm1 = fmaxf(pm1, __shfl_xor_sync(0xffffffffu, pm1, 1));
        pm1 = fmaxf(pm1, __shfl_xor_sync(0xffffffffu, pm1, 2));

        float nm0 = fmaxf(m0, pm0), nm1 = fmaxf(m1, pm1);
        float al0 = __expf(m0 - nm0), al1 = __expf(m1 - nm1);

        // ---- P = tf32(exp(S - m)) in-place; row sums ----
        float ps0 = 0.f, ps1 = 0.f;
        #pragma unroll
        for (int nt = 0; nt < 8; nt++) {
            float px = tf32r(__expf(S4[nt].x - nm0));
            float py = tf32r(__expf(S4[nt].y - nm0));
            float pz = tf32r(__expf(S4[nt].z - nm1));
            float pw = tf32r(__expf(S4[nt].w - nm1));
            S4[nt] = make_float4(px, py, pz, pw);
            ps0 += px + py; ps1 += pz + pw;
        }
        ps0 += __shfl_xor_sync(0xffffffffu, ps0, 1);
        ps0 += __shfl_xor_sync(0xffffffffu, ps0, 2);
        ps1 += __shfl_xor_sync(0xffffffffu, ps1, 1);
        ps1 += __shfl_xor_sync(0xffffffffu, ps1, 2);
        l0 = l0 * al0 + ps0; l1 = l1 * al1 + ps1;
        m0 = nm0; m1 = nm1;

        // ---- O = O*alpha + P @ V (P from registers: acc layout == A layout) ----
        #pragma unroll
        for (int nt = 0; nt < 9; nt++) {
            O[nt].x *= al0; O[nt].y *= al0; O[nt].z *= al1; O[nt].w *= al1;
        }
        #pragma unroll
        for (int kk = 0; kk < 8; kk++) {
            unsigned a0 = F2U(S4[kk].x), a1 = F2U(S4[kk].z);
            unsigned a2 = F2U(S4[kk].y), a3 = F2U(S4[kk].w);
            const int kb = kk * 8 + 2 * c;
            #pragma unroll
            for (int nt = 0; nt < 9; nt++) {
                float2 bb = *(const float2*)(Vt + (nt * 8 + r) * 72 + kb);
                mma_tf32(O[nt], a0, a1, a2, a3, F2U(bb.x), F2U(bb.y));
            }
        }
    }

    // ---- epilogue: divide by l, store [b, n, h*72 + d] ----
    float inv0 = 1.0f / l0, inv1 = 1.0f / l1;
    float* op0 = g_ao + (size_t)(b * N_ + q0 + r) * C_ + h * HD_;
    float* op1 = op0 + (size_t)8 * C_;
    #pragma unroll
    for (int nt = 0; nt < 9; nt++) {
        int d0 = nt * 8 + 2 * c;
        *(float2*)(op0 + d0) = make_float2(O[nt].x * inv0, O[nt].y * inv0);
        *(float2*)(op1 + d0) = make_float2(O[nt].z * inv1, O[nt].w * inv1);
    }
}

// ---------------------------------------------------------------------------
// Kernel 3: proj GEMM (NT) + bias. M=4096, Nj=1152, K=1152. Same scheme as qkv.
// ---------------------------------------------------------------------------
__global__ __launch_bounds__(256, 2) void proj_kernel(const float* __restrict__ w,
                                                      const float* __restrict__ bias,
                                                      float* __restrict__ out) {
    __shared__ float As[2][128 * 24];
    __shared__ float Bs[2][128 * 24];
    const int t = threadIdx.x, l = t & 31, wid = t >> 5;
    const int wm = wid >> 2, wn = wid & 3;
    const int r = l >> 2, c = l & 3;
    const int lrow = t >> 2, lseg = t & 3;
    const float* Ab = g_ao + (size_t)blockIdx.y * 128 * C_ + lrow * C_ + lseg * 4;
    const float* Bb = w    + (size_t)blockIdx.x * 128 * C_ + lrow * C_ + lseg * 4;

    float4 acc[4][4];
    #pragma unroll
    for (int i = 0; i < 4; i++)
        #pragma unroll
        for (int j = 0; j < 4; j++) acc[i][j] = make_float4(0.f, 0.f, 0.f, 0.f);

    float4 ra0 = *(const float4*)(Ab);
    float4 ra1 = *(const float4*)(Ab + 64 * C_);
    float4 rb0 = *(const float4*)(Bb);
    float4 rb1 = *(const float4*)(Bb + 64 * C_);
    cvst(&As[0][lrow * 24 + lseg * 4], ra0);
    cvst(&As[0][(lrow + 64) * 24 + lseg * 4], ra1);
    cvst(&Bs[0][lrow * 24 + lseg * 4], rb0);
    cvst(&Bs[0][(lrow + 64) * 24 + lseg * 4], rb1);

    for (int k0 = 16; k0 <= C_; k0 += 16) {
        const int pb = ((k0 >> 4) + 1) & 1;
        if (k0 < C_) {
            ra0 = *(const float4*)(Ab + k0);
            ra1 = *(const float4*)(Ab + 64 * C_ + k0);
            rb0 = *(const float4*)(Bb + k0);
            rb1 = *(const float4*)(Bb + 64 * C_ + k0);
        }
        __syncthreads();
        const float* Ap = As[pb];
        const float* Bp = Bs[pb];
        #pragma unroll
        for (int ks = 0; ks < 16; ks += 8) {
            unsigned a0[4], a1[4], a2[4], a3[4];
            #pragma unroll
            for (int mt = 0; mt < 4; mt++) {
                const float* q0 = Ap + (wm * 64 + mt * 16 + r) * 24 + ks + 2 * c;
                float2 la = *(const float2*)q0;
                float2 lb = *(const float2*)(q0 + 8 * 24);
                a0[mt] = F2U(la.x); a1[mt] = F2U(lb.x);
                a2[mt] = F2U(la.y); a3[mt] = F2U(lb.y);
            }
            #pragma unroll
            for (int nt = 0; nt < 4; nt++) {
                float2 bb = *(const float2*)(Bp + (wn * 32 + nt * 8 + r) * 24 + ks + 2 * c);
                unsigned b0 = F2U(bb.x), b1 = F2U(bb.y);
                #pragma unroll
                for (int mt = 0; mt < 4; mt++)
                    mma_tf32(acc[mt][nt], a0[mt], a1[mt], a2[mt], a3[mt], b0, b1);
            }
        }
        if (k0 < C_) {
            const int pn = pb ^ 1;
            cvst(&As[pn][lrow * 24 + lseg * 4], ra0);
            cvst(&As[pn][(lrow + 64) * 24 + lseg * 4], ra1);
            cvst(&Bs[pn][lrow * 24 + lseg * 4], rb0);
            cvst(&Bs[pn][(lrow + 64) * 24 + lseg * 4], rb1);
        }
    }

    #pragma unroll
    for (int mt = 0; mt < 4; mt++) {
        int m0 = blockIdx.y * 128 + wm * 64 + mt * 16 + r;
        #pragma unroll
        for (int nt = 0; nt < 4; nt++) {
            int col0 = blockIdx.x * 128 + wn * 32 + nt * 8 + c * 2;
            float bv0 = bias[col0], bv1 = bias[col0 + 1];
            out[(size_t)m0 * C_ + col0]           = acc[mt][nt].x + bv0;
            out[(size_t)m0 * C_ + col0 + 1]       = acc[mt][nt].y + bv1;
            out[(size_t)(m0 + 8) * C_ + col0]     = acc[mt][nt].z + bv0;
            out[(size_t)(m0 + 8) * C_ + col0 + 1] = acc[mt][nt].w + bv1;
        }
    }
}

// ---------------------------------------------------------------------------
extern "C" void kernel_launch(void* const* d_in, const int* in_sizes, int n_in,
                              void* d_out, int out_size) {
    const float* x      = (const float*)d_in[0];
    const int*   amask  = (const int*)  d_in[1];
    const float* w_qkv  = (const float*)d_in[2];
    const float* w_proj = (const float*)d_in[3];
    const float* b_proj = (const float*)d_in[4];
    float* out = (float*)d_out;

    const int attn_smem = (128 * 72 + 64 * 72 + 72 * 72) * 4 + 64 * 4;  // 76,288 B
    cudaFuncSetAttribute(attn_kernel, cudaFuncAttributeMaxDynamicSharedMemorySize, attn_smem);

    qkv_kernel<<<dim3(27, 32), 256>>>(x, w_qkv);
    attn_kernel<<<dim3(16, 16, 2), 256, attn_smem>>>(amask);
    proj_kernel<<<dim3(9, 32), 256>>>(w_proj, b_proj, out);
}

// round 13
// speedup vs baseline: 3.3802x; 1.1492x over previous
#include <cuda_runtime.h>
#include <cstdint>

// Fused MHA: B=2, N=2048, C=1152, H=16, HD=72
// Round-13: tf32 mma.m16n8k8 + cp.async double-buffered pipelines.
//  - pre-round kernel: x / w_qkv / w_proj -> tf32 once (enables raw cp.async).
//  - GEMMs: BK=32, cp.async 2-stage, 1 barrier/slice, stride-40 smem.
//  - attention: Q-tile 256, warp owns 32 rows (2x fragment reuse -> smem bytes
//    below tensor floor), cp.async K/V double buffer, 1 barrier/tile,
//    P reused from S accumulators, warp-local softmax in registers.

#define B_   2
#define N_   2048
#define C_   1152
#define H_   16
#define HD_  72
#define HD2_ 80
#define NEG_ (-100000000.0f)
#define SCALE_ 0.11785113019775793f   // 72^-0.5

__device__ float g_q [B_*H_*N_*HD2_];   // tf32, Q pre-scaled
__device__ float g_k [B_*H_*N_*HD2_];   // tf32
__device__ float g_vt[B_*H_*HD_*N_];    // tf32, transposed [B][H][HD][N]
__device__ float g_ao[B_*N_*C_];        // tf32 (rounded in attn epilogue)
__device__ float g_xr[B_*N_*C_];        // tf32 pre-rounded x
__device__ float g_wq[3*C_*C_];         // tf32 pre-rounded w_qkv
__device__ float g_wp[C_*C_];           // tf32 pre-rounded w_proj

__device__ __forceinline__ float tf32r(float x) {
    unsigned u;
    asm("cvt.rna.tf32.f32 %0, %1;" : "=r"(u) : "f"(x));
    return __uint_as_float(u);
}

__device__ __forceinline__ void mma_tf32(float4& d, unsigned a0, unsigned a1,
                                         unsigned a2, unsigned a3,
                                         unsigned b0, unsigned b1) {
    asm volatile("mma.sync.aligned.m16n8k8.row.col.f32.tf32.tf32.f32 "
                 "{%0,%1,%2,%3},{%4,%5,%6,%7},{%8,%9},{%0,%1,%2,%3};"
                 : "+f"(d.x), "+f"(d.y), "+f"(d.z), "+f"(d.w)
                 : "r"(a0), "r"(a1), "r"(a2), "r"(a3), "r"(b0), "r"(b1));
}

#define F2U __float_as_uint

__device__ __forceinline__ void cpa16(uint32_t daddr, const void* src) {
    asm volatile("cp.async.cg.shared.global [%0], [%1], 16;"
                 :: "r"(daddr), "l"(src));
}
#define CP_COMMIT() asm volatile("cp.async.commit_group;")
#define CP_WAIT0()  asm volatile("cp.async.wait_group 0;" ::: "memory")

// ---------------------------------------------------------------------------
// Kernel 0: elementwise tf32 rounding (one-time; enables raw cp.async in GEMMs)
// ---------------------------------------------------------------------------
__global__ void round_kernel(const float4* __restrict__ src,
                             float4* __restrict__ dst, int n4) {
    int i = blockIdx.x * 256 + threadIdx.x;
    if (i < n4) {
        float4 v = src[i];
        dst[i] = make_float4(tf32r(v.x), tf32r(v.y), tf32r(v.z), tf32r(v.w));
    }
}

// ---------------------------------------------------------------------------
// Kernel 1: QKV GEMM (NT). M=4096, Nj=3456, K=1152. Block 128x128, BK=32,
// 8 warps (2M x 4N), warp 64x32. cp.async 2-stage, stride-40 smem.
// Epilogue: Q (scaled)/K -> [B][H][N][80] tf32; V transposed -> [B][H][HD][N].
// ---------------------------------------------------------------------------
__global__ __launch_bounds__(256, 2) void qkv_kernel(const float* __restrict__ xr,
                                                     const float* __restrict__ wr) {
    extern __shared__ float smg[];
    float* As = smg;                 // 2 x [128][40]
    float* Bs = smg + 2 * 128 * 40;
    const int t = threadIdx.x, l = t & 31, wid = t >> 5;
    const int wm = wid >> 2, wn = wid & 3;
    const int r = l >> 2, c = l & 3;
    const int lrow = t >> 1, lseg = t & 1;
    const float* Asrc = xr + ((size_t)blockIdx.y * 128 + lrow) * C_;
    const float* Bsrc = wr + ((size_t)blockIdx.x * 128 + lrow) * C_;
    const uint32_t as_a = (uint32_t)__cvta_generic_to_shared(As) + lrow * 40 * 4;
    const uint32_t bs_a = (uint32_t)__cvta_generic_to_shared(Bs) + lrow * 40 * 4;

    float4 acc[4][4];
    #pragma unroll
    for (int i = 0; i < 4; i++)
        #pragma unroll
        for (int j = 0; j < 4; j++) acc[i][j] = make_float4(0.f, 0.f, 0.f, 0.f);

    auto issue = [&](int tt) {
        const int so = (tt & 1) * 5120 * 4;
        #pragma unroll
        for (int k2 = 0; k2 < 4; k2++) {
            int s = lseg + 2 * k2;
            cpa16(as_a + so + s * 16, Asrc + tt * 32 + s * 4);
            cpa16(bs_a + so + s * 16, Bsrc + tt * 32 + s * 4);
        }
    };
    issue(0); CP_COMMIT();

    for (int tt = 0; tt < 36; tt++) {
        CP_WAIT0(); __syncthreads();
        if (tt < 35) { issue(tt + 1); CP_COMMIT(); }
        const float* Ap = As + (tt & 1) * 5120;
        const float* Bp = Bs + (tt & 1) * 5120;
        #pragma unroll
        for (int ks = 0; ks < 32; ks += 8) {
            unsigned a0[4], a1[4], a2[4], a3[4];
            #pragma unroll
            for (int mt = 0; mt < 4; mt++) {
                const float* q0 = Ap + (wm * 64 + mt * 16 + r) * 40 + ks + 2 * c;
                float2 la = *(const float2*)q0;
                float2 lb = *(const float2*)(q0 + 8 * 40);
                a0[mt] = F2U(la.x); a1[mt] = F2U(lb.x);
                a2[mt] = F2U(la.y); a3[mt] = F2U(lb.y);
            }
            #pragma unroll
            for (int nt = 0; nt < 4; nt++) {
                float2 bb = *(const float2*)(Bp + (wn * 32 + nt * 8 + r) * 40 + ks + 2 * c);
                unsigned b0 = F2U(bb.x), b1 = F2U(bb.y);
                #pragma unroll
                for (int mt = 0; mt < 4; mt++)
                    mma_tf32(acc[mt][nt], a0[mt], a1[mt], a2[mt], a3[mt], b0, b1);
            }
        }
    }

    // Epilogue: tile width 128 never crosses q/k/v boundary (1152 = 9*128).
    const int part = (blockIdx.x * 128) / C_;
    const float sc = (part == 0) ? SCALE_ : 1.0f;
    #pragma unroll
    for (int mt = 0; mt < 4; mt++) {
        int m0 = blockIdx.y * 128 + wm * 64 + mt * 16 + r;
        #pragma unroll
        for (int nt = 0; nt < 4; nt++) {
            int col0 = blockIdx.x * 128 - part * C_ + wn * 32 + nt * 8 + c * 2;
            float v[4] = {acc[mt][nt].x, acc[mt][nt].y, acc[mt][nt].z, acc[mt][nt].w};
            #pragma unroll
            for (int e = 0; e < 4; e++) {
                int m  = m0 + (e >> 1) * 8;
                int jj = col0 + (e & 1);
                int hh = jj / HD_;
                int dd = jj - hh * HD_;
                int bb = m >> 11;
                int nn = m & (N_ - 1);
                float val = tf32r(v[e] * sc);
                if (part == 0)
                    g_q[((size_t)(bb * H_ + hh) * N_ + nn) * HD2_ + dd] = val;
                else if (part == 1)
                    g_k[((size_t)(bb * H_ + hh) * N_ + nn) * HD2_ + dd] = val;
                else
                    g_vt[((size_t)(bb * H_ + hh) * HD_ + dd) * N_ + nn] = val;
            }
        }
    }
}

// ---------------------------------------------------------------------------
// Kernel 2: flash attention. One CTA = 256 q rows of one (b,h). 8 warps,
// warp owns 32 rows (mt=0,1 of 16). KV tile 64, cp.async double-buffered,
// 1 barrier/tile. P from S accumulators; V transposed; softmax in registers.
// Dyn smem 152,576 B -> 1 CTA/SM.
// ---------------------------------------------------------------------------
__global__ __launch_bounds__(256, 1) void attn_kernel(const int* __restrict__ mask) {
    extern __shared__ float smg[];
    float* Qs = smg;                        // [256][72]
    float* Ks = smg + 256 * 72;             // 2 x [64][72]
    float* Vt = Ks + 2 * 64 * 72;           // 2 x [72][72] (cols 0..63 used)
    int*   mk = (int*)(Vt + 2 * 72 * 72);   // 2 x [64]

    const int t = threadIdx.x, l = t & 31, wid = t >> 5;
    const int r = l >> 2, c = l & 3;
    const int qt = blockIdx.x, h = blockIdx.y, b = blockIdx.z;
    const int bh = b * H_ + h;
    const float* qp  = g_q  + ((size_t)bh * N_ + qt * 256) * HD2_;
    const float* kp  = g_k  + (size_t)bh * N_ * HD2_;
    const float* vtp = g_vt + (size_t)bh * HD_ * N_;
    const int*   mp  = mask + b * N_;

    const uint32_t ks_a = (uint32_t)__cvta_generic_to_shared(Ks);
    const uint32_t vt_a = (uint32_t)__cvta_generic_to_shared(Vt);
    const uint32_t mk_a = (uint32_t)__cvta_generic_to_shared(mk);
    const int krow = t >> 2, kseg = t & 3;

    // Q tile (one-time)
    for (int i = t; i < 256 * 18; i += 256) {
        int row = i / 18, s = i - row * 18;
        *(float4*)&Qs[row * 72 + s * 4] = *(const float4*)(qp + (size_t)row * HD2_ + s * 4);
    }
    const int q0 = qt * 256 + wid * 32;
    int mq[4];
    #pragma unroll
    for (int i = 0; i < 4; i++) mq[i] = mp[q0 + (i >> 1) * 16 + (i & 1) * 8 + r];

    float4 O[2][9];
    #pragma unroll
    for (int mt = 0; mt < 2; mt++)
        #pragma unroll
        for (int nt = 0; nt < 9; nt++) O[mt][nt] = make_float4(0.f, 0.f, 0.f, 0.f);
    float mrun[4] = {-3.0e38f, -3.0e38f, -3.0e38f, -3.0e38f};
    float lrun[4] = {0.f, 0.f, 0.f, 0.f};

    auto issue = [&](int tt) {
        const int sel = tt & 1;
        uint32_t kd = ks_a + (sel * 4608 + krow * 72) * 4;
        const float* ksrc = kp + (size_t)(tt * 64 + krow) * HD2_;
        #pragma unroll
        for (int k2 = 0; k2 < 4; k2++)
            cpa16(kd + (kseg + 4 * k2) * 16, ksrc + (kseg + 4 * k2) * 4);
        if (kseg < 2) cpa16(kd + (16 + kseg) * 16, ksrc + (16 + kseg) * 4);
        #pragma unroll
        for (int j = 0; j < 4; j++) {
            int idx = t + j * 256;
            int vrow = idx >> 4, vs = idx & 15;
            cpa16(vt_a + (sel * 5184 + vrow * 72 + vs * 4) * 4,
                  vtp + (size_t)vrow * N_ + tt * 64 + vs * 4);
        }
        if (t < 128) {
            int idx = 1024 + t;
            int vrow = idx >> 4, vs = idx & 15;
            cpa16(vt_a + (sel * 5184 + vrow * 72 + vs * 4) * 4,
                  vtp + (size_t)vrow * N_ + tt * 64 + vs * 4);
        }
        if (t < 16) cpa16(mk_a + (sel * 64 + t * 4) * 4, mp + tt * 64 + t * 4);
    };
    issue(0); CP_COMMIT();

    const float* qbase = Qs + (wid * 32 + r) * 72 + 2 * c;

    for (int kt = 0; kt < 32; kt++) {
        CP_WAIT0(); __syncthreads();
        if (kt < 31) { issue(kt + 1); CP_COMMIT(); }
        const float* Kb  = Ks + (kt & 1) * 4608;
        const float* Vb  = Vt + (kt & 1) * 5184;
        const int*   mkb = mk + (kt & 1) * 64;

        // ---- S = Q K^T ----
        float4 S4[2][8];
        #pragma unroll
        for (int mt = 0; mt < 2; mt++)
            #pragma unroll
            for (int nt = 0; nt < 8; nt++) S4[mt][nt] = make_float4(0.f, 0.f, 0.f, 0.f);
        #pragma unroll
        for (int ks = 0; ks < 9; ks++) {
            const int kb = ks * 8;
            unsigned a0[2], a1[2], a2[2], a3[2];
            #pragma unroll
            for (int mt = 0; mt < 2; mt++) {
                float2 la = *(const float2*)(qbase + mt * 16 * 72 + kb);
                float2 lb = *(const float2*)(qbase + (mt * 16 + 8) * 72 + kb);
                a0[mt] = F2U(la.x); a1[mt] = F2U(lb.x);
                a2[mt] = F2U(la.y); a3[mt] = F2U(lb.y);
            }
            #pragma unroll
            for (int nt = 0; nt < 8; nt++) {
                float2 bb = *(const float2*)(Kb + (nt * 8 + r) * 72 + kb + 2 * c);
                unsigned b0 = F2U(bb.x), b1 = F2U(bb.y);
                #pragma unroll
                for (int mt = 0; mt < 2; mt++)
                    mma_tf32(S4[mt][nt], a0[mt], a1[mt], a2[mt], a3[mt], b0, b1);
            }
        }

        // ---- softmax (warp-local, registers) ----
        float al[4];
        #pragma unroll
        for (int mt = 0; mt < 2; mt++) {
            const int mqa = mq[mt * 2], mqb = mq[mt * 2 + 1];
            float pm0 = -3.0e38f, pm1 = -3.0e38f;
            #pragma unroll
            for (int nt = 0; nt < 8; nt++) {
                int cc = nt * 8 + 2 * c;
                int mk0 = mkb[cc], mk1 = mkb[cc + 1];
                float4& s = S4[mt][nt];
                s.x += (mqa && mk0) ? 0.f : NEG_;
                s.y += (mqa && mk1) ? 0.f : NEG_;
                s.z += (mqb && mk0) ? 0.f : NEG_;
                s.w += (mqb && mk1) ? 0.f : NEG_;
                pm0 = fmaxf(pm0, fmaxf(s.x, s.y));
                pm1 = fmaxf(pm1, fmaxf(s.z, s.w));
            }
            pm0 = fmaxf(pm0, __shfl_xor_sync(0xffffffffu, pm0, 1));
            pm0 = fmaxf(pm0, __shfl_xor_sync(0xffffffffu, pm0, 2));
            pm1 = fmaxf(pm1, __shfl_xor_sync(0xffffffffu, pm1, 1));
            pm1 = fmaxf(pm1, __shfl_xor_sync(0xffffffffu, pm1, 2));
            float nm0 = fmaxf(mrun[mt * 2], pm0);
            float nm1 = fmaxf(mrun[mt * 2 + 1], pm1);
            float a0 = __expf(mrun[mt * 2] - nm0);
            float a1 = __expf(mrun[mt * 2 + 1] - nm1);
            float ps0 = 0.f, ps1 = 0.f;
            #pragma unroll
            for (int nt = 0; nt < 8; nt++) {
                float4& s = S4[mt][nt];
                float px = tf32r(__expf(s.x - nm0));
                float py = tf32r(__expf(s.y - nm0));
                float pz = tf32r(__expf(s.z - nm1));
                float pw = tf32r(__expf(s.w - nm1));
                s = make_float4(px, py, pz, pw);
                ps0 += px + py; ps1 += pz + pw;
            }
            ps0 += __shfl_xor_sync(0xffffffffu, ps0, 1);
            ps0 += __shfl_xor_sync(0xffffffffu, ps0, 2);
            ps1 += __shfl_xor_sync(0xffffffffu, ps1, 1);
            ps1 += __shfl_xor_sync(0xffffffffu, ps1, 2);
            lrun[mt * 2]     = lrun[mt * 2] * a0 + ps0;
            lrun[mt * 2 + 1] = lrun[mt * 2 + 1] * a1 + ps1;
            mrun[mt * 2]     = nm0;
            mrun[mt * 2 + 1] = nm1;
            al[mt * 2] = a0; al[mt * 2 + 1] = a1;
        }

        // ---- O = O*alpha + P @ V (P from accumulators) ----
        #pragma unroll
        for (int mt = 0; mt < 2; mt++)
            #pragma unroll
            for (int nt = 0; nt < 9; nt++) {
                O[mt][nt].x *= al[mt * 2];     O[mt][nt].y *= al[mt * 2];
                O[mt][nt].z *= al[mt * 2 + 1]; O[mt][nt].w *= al[mt * 2 + 1];
            }
        #pragma unroll
        for (int kk = 0; kk < 8; kk++) {
            unsigned pa0[2], pa1[2], pa2[2], pa3[2];
            #pragma unroll
            for (int mt = 0; mt < 2; mt++) {
                pa0[mt] = F2U(S4[mt][kk].x); pa1[mt] = F2U(S4[mt][kk].z);
                pa2[mt] = F2U(S4[mt][kk].y); pa3[mt] = F2U(S4[mt][kk].w);
            }
            const int kb2 = kk * 8 + 2 * c;
            #pragma unroll
            for (int nt = 0; nt < 9; nt++) {
                float2 bb = *(const float2*)(Vb + (nt * 8 + r) * 72 + kb2);
                unsigned b0 = F2U(bb.x), b1 = F2U(bb.y);
                #pragma unroll
                for (int mt = 0; mt < 2; mt++)
                    mma_tf32(O[mt][nt], pa0[mt], pa1[mt], pa2[mt], pa3[mt], b0, b1);
            }
        }
    }

    // ---- epilogue: /l, tf32-round (proj reads via cp.async), store ----
    #pragma unroll
    for (int mt = 0; mt < 2; mt++) {
        float inv0 = 1.0f / lrun[mt * 2];
        float inv1 = 1.0f / lrun[mt * 2 + 1];
        float* op0 = g_ao + (size_t)(b * N_ + q0 + mt * 16 + r) * C_ + h * HD_;
        float* op1 = op0 + (size_t)8 * C_;
        #pragma unroll
        for (int nt = 0; nt < 9; nt++) {
            int d0 = nt * 8 + 2 * c;
            *(float2*)(op0 + d0) = make_float2(tf32r(O[mt][nt].x * inv0),
                                               tf32r(O[mt][nt].y * inv0));
            *(float2*)(op1 + d0) = make_float2(tf32r(O[mt][nt].z * inv1),
                                               tf32r(O[mt][nt].w * inv1));
        }
    }
}

// ---------------------------------------------------------------------------
// Kernel 3: proj GEMM (NT) + bias. M=4096, Nj=1152, K=1152. Same as qkv.
// ---------------------------------------------------------------------------
__global__ __launch_bounds__(256, 2) void proj_kernel(const float* __restrict__ wr,
                                                      const float* __restrict__ bias,
                                                      float* __restrict__ out) {
    extern __shared__ float smg[];
    float* As = smg;
    float* Bs = smg + 2 * 128 * 40;
    const int t = threadIdx.x, l = t & 31, wid = t >> 5;
    const int wm = wid >> 2, wn = wid & 3;
    const int r = l >> 2, c = l & 3;
    const int lrow = t >> 1, lseg = t & 1;
    const float* Asrc = g_ao + ((size_t)blockIdx.y * 128 + lrow) * C_;
    const float* Bsrc = wr   + ((size_t)blockIdx.x * 128 + lrow) * C_;
    const uint32_t as_a = (uint32_t)__cvta_generic_to_shared(As) + lrow * 40 * 4;
    const uint32_t bs_a = (uint32_t)__cvta_generic_to_shared(Bs) + lrow * 40 * 4;

    float4 acc[4][4];
    #pragma unroll
    for (int i = 0; i < 4; i++)
        #pragma unroll
        for (int j = 0; j < 4; j++) acc[i][j] = make_float4(0.f, 0.f, 0.f, 0.f);

    auto issue = [&](int tt) {
        const int so = (tt & 1) * 5120 * 4;
        #pragma unroll
        for (int k2 = 0; k2 < 4; k2++) {
            int s = lseg + 2 * k2;
            cpa16(as_a + so + s * 16, Asrc + tt * 32 + s * 4);
            cpa16(bs_a + so + s * 16, Bsrc + tt * 32 + s * 4);
        }
    };
    issue(0); CP_COMMIT();

    for (int tt = 0; tt < 36; tt++) {
        CP_WAIT0(); __syncthreads();
        if (tt < 35) { issue(tt + 1); CP_COMMIT(); }
        const float* Ap = As + (tt & 1) * 5120;
        const float* Bp = Bs + (tt & 1) * 5120;
        #pragma unroll
        for (int ks = 0; ks < 32; ks += 8) {
            unsigned a0[4], a1[4], a2[4], a3[4];
            #pragma unroll
            for (int mt = 0; mt < 4; mt++) {
                const float* q0 = Ap + (wm * 64 + mt * 16 + r) * 40 + ks + 2 * c;
                float2 la = *(const float2*)q0;
                float2 lb = *(const float2*)(q0 + 8 * 40);
                a0[mt] = F2U(la.x); a1[mt] = F2U(lb.x);
                a2[mt] = F2U(la.y); a3[mt] = F2U(lb.y);
            }
            #pragma unroll
            for (int nt = 0; nt < 4; nt++) {
                float2 bb = *(const float2*)(Bp + (wn * 32 + nt * 8 + r) * 40 + ks + 2 * c);
                unsigned b0 = F2U(bb.x), b1 = F2U(bb.y);
                #pragma unroll
                for (int mt = 0; mt < 4; mt++)
                    mma_tf32(acc[mt][nt], a0[mt], a1[mt], a2[mt], a3[mt], b0, b1);
            }
        }
    }

    #pragma unroll
    for (int mt = 0; mt < 4; mt++) {
        int m0 = blockIdx.y * 128 + wm * 64 + mt * 16 + r;
        #pragma unroll
        for (int nt = 0; nt < 4; nt++) {
            int col0 = blockIdx.x * 128 + wn * 32 + nt * 8 + c * 2;
            float bv0 = bias[col0], bv1 = bias[col0 + 1];
            out[(size_t)m0 * C_ + col0]           = acc[mt][nt].x + bv0;
            out[(size_t)m0 * C_ + col0 + 1]       = acc[mt][nt].y + bv1;
            out[(size_t)(m0 + 8) * C_ + col0]     = acc[mt][nt].z + bv0;
            out[(size_t)(m0 + 8) * C_ + col0 + 1] = acc[mt][nt].w + bv1;
        }
    }
}

// ---------------------------------------------------------------------------
extern "C" void kernel_launch(void* const* d_in, const int* in_sizes, int n_in,
                              void* d_out, int out_size) {
    const float* x      = (const float*)d_in[0];
    const int*   amask  = (const int*)  d_in[1];
    const float* w_qkv  = (const float*)d_in[2];
    const float* w_proj = (const float*)d_in[3];
    const float* b_proj = (const float*)d_in[4];
    float* out = (float*)d_out;

    const int gemm_smem = 2 * (2 * 128 * 40) * 4;                     // 81,920 B
    const int attn_smem = (256*72 + 2*64*72 + 2*72*72 + 128) * 4;     // 152,576 B
    cudaFuncSetAttribute(qkv_kernel,  cudaFuncAttributeMaxDynamicSharedMemorySize, gemm_smem);
    cudaFuncSetAttribute(proj_kernel, cudaFuncAttributeMaxDynamicSharedMemorySize, gemm_smem);
    cudaFuncSetAttribute(attn_kernel, cudaFuncAttributeMaxDynamicSharedMemorySize, attn_smem);

    float* xr; float* wq; float* wp;
    cudaGetSymbolAddress((void**)&xr, g_xr);
    cudaGetSymbolAddress((void**)&wq, g_wq);
    cudaGetSymbolAddress((void**)&wp, g_wp);

    const int n4x = B_*N_*C_/4, n4q = 3*C_*C_/4, n4p = C_*C_/4;
    round_kernel<<<(n4x + 255)/256, 256>>>((const float4*)x,      (float4*)xr, n4x);
    round_kernel<<<(n4q + 255)/256, 256>>>((const float4*)w_qkv,  (float4*)wq, n4q);
    round_kernel<<<(n4p + 255)/256, 256>>>((const float4*)w_proj, (float4*)wp, n4p);

    qkv_kernel <<<dim3(27, 32),   256, gemm_smem>>>(xr, wq);
    attn_kernel<<<dim3(8, 16, 2), 256, attn_smem>>>(amask);
    proj_kernel<<<dim3(9, 32),    256, gemm_smem>>>(wp, b_proj, out);
}

// round 16
// speedup vs baseline: 4.5820x; 1.3555x over previous
#include <cuda_runtime.h>
#include <cstdint>

// Fused MHA B=2,N=2048,C=1152,H=16,HD=72. Round-16: tf32 mma.sync (tcgen05
// rejected by harness ptxas target sm_103) + MASK COMPACTION: skip masked
// keys/queries in attention (their softmax contribution is exactly 0 / exactly
// uniform in fp32), cutting attention MACs ~4x.

#define B_   2
#define N_   2048
#define C_   1152
#define H_   16
#define HD_  72
#define HD2_ 80
#define NEG_ (-100000000.0f)
#define SCALE_ 0.11785113019775793f

__device__ float g_q [B_*H_*N_*HD2_];   // tf32, Q pre-scaled, COMPACTED rows
__device__ float g_k [B_*H_*N_*HD2_];   // tf32, compacted rows
__device__ float g_vt[B_*H_*HD_*N_];    // tf32, transposed, compacted cols
__device__ float g_ao[B_*N_*C_];        // tf32 attention out (original order)
__device__ float g_xr[B_*N_*C_];
__device__ float g_wq[3*C_*C_];
__device__ float g_wp[C_*C_];
__device__ float g_vmean[B_*C_];        // [b][h*72+d] mean of V over keys
__device__ int   g_cnt[B_];             // unmasked count per batch
__device__ int   g_cpos[B_*N_];         // original n -> compacted pos
__device__ int   g_cidx[B_*N_];         // compacted pos -> original n

__device__ __forceinline__ float tf32r(float x) {
    unsigned u; asm("cvt.rna.tf32.f32 %0, %1;" : "=r"(u) : "f"(x));
    return __uint_as_float(u);
}
__device__ __forceinline__ void mma_tf32(float4& d, unsigned a0, unsigned a1,
                                         unsigned a2, unsigned a3,
                                         unsigned b0, unsigned b1) {
    asm volatile("mma.sync.aligned.m16n8k8.row.col.f32.tf32.tf32.f32 "
                 "{%0,%1,%2,%3},{%4,%5,%6,%7},{%8,%9},{%0,%1,%2,%3};"
                 : "+f"(d.x), "+f"(d.y), "+f"(d.z), "+f"(d.w)
                 : "r"(a0), "r"(a1), "r"(a2), "r"(a3), "r"(b0), "r"(b1));
}
#define F2U __float_as_uint
__device__ __forceinline__ void cpa16(uint32_t d, const void* s) {
    asm volatile("cp.async.cg.shared.global [%0], [%1], 16;" :: "r"(d), "l"(s));
}
#define CP_COMMIT() asm volatile("cp.async.commit_group;")
#define CP_WAIT0()  asm volatile("cp.async.wait_group 0;" ::: "memory")

// ---- Kernel A: per-batch mask compaction (stable): unmasked first ----
__global__ void compact_kernel(const int* __restrict__ mask) {
    const int b = blockIdx.x, t = threadIdx.x;          // 256 threads
    __shared__ int wsum[8];
    __shared__ int s_cnt;
    const int* mp = mask + b * N_;
    int v[8], tot = 0;
    const int base = t * 8;
    #pragma unroll
    for (int i = 0; i < 8; i++) { v[i] = mp[base + i]; tot += v[i]; }
    const int lane = t & 31, w = t >> 5;
    int pre = tot;
    #pragma unroll
    for (int o = 1; o < 32; o <<= 1) {
        int n = __shfl_up_sync(0xffffffffu, pre, o);
        if (lane >= o) pre += n;
    }
    if (lane == 31) wsum[w] = pre;
    __syncthreads();
    if (t == 0) {
        int acc = 0;
        #pragma unroll
        for (int i = 0; i < 8; i++) { int x = wsum[i]; wsum[i] = acc; acc += x; }
        s_cnt = acc;
    }
    __syncthreads();
    int excl = wsum[w] + (pre - tot);
    const int cnt = s_cnt;
    #pragma unroll
    for (int i = 0; i < 8; i++) {
        int idx = base + i;
        int pos = v[i] ? excl : cnt + (idx - excl);
        g_cpos[b * N_ + idx] = pos;
        g_cidx[b * N_ + pos] = idx;
        excl += v[i];
    }
    if (t == 0) g_cnt[b] = cnt;
}

// ---- Kernel B: tf32 preround ----
__global__ void round_kernel(const float4* __restrict__ src,
                             float4* __restrict__ dst, int n4) {
    int i = blockIdx.x * 256 + threadIdx.x;
    if (i < n4) {
        float4 v = src[i];
        dst[i] = make_float4(tf32r(v.x), tf32r(v.y), tf32r(v.z), tf32r(v.w));
    }
}

// ---- Kernel C: QKV GEMM (R13 tf32 pipeline) + compacted scatter ----
__global__ __launch_bounds__(256, 2) void qkv_kernel(const float* __restrict__ xr,
                                                     const float* __restrict__ wr) {
    extern __shared__ float smg[];
    float* As = smg;
    float* Bs = smg + 2 * 128 * 40;
    const int t = threadIdx.x, l = t & 31, wid = t >> 5;
    const int wm = wid >> 2, wn = wid & 3;
    const int r = l >> 2, c = l & 3;
    const int lrow = t >> 1, lseg = t & 1;
    const float* Asrc = xr + ((size_t)blockIdx.y * 128 + lrow) * C_;
    const float* Bsrc = wr + ((size_t)blockIdx.x * 128 + lrow) * C_;
    const uint32_t as_a = (uint32_t)__cvta_generic_to_shared(As) + lrow * 40 * 4;
    const uint32_t bs_a = (uint32_t)__cvta_generic_to_shared(Bs) + lrow * 40 * 4;

    float4 acc[4][4];
    #pragma unroll
    for (int i = 0; i < 4; i++)
        #pragma unroll
        for (int j = 0; j < 4; j++) acc[i][j] = make_float4(0.f, 0.f, 0.f, 0.f);

    auto issue = [&](int tt) {
        const int so = (tt & 1) * 5120 * 4;
        #pragma unroll
        for (int k2 = 0; k2 < 4; k2++) {
            int s = lseg + 2 * k2;
            cpa16(as_a + so + s * 16, Asrc + tt * 32 + s * 4);
            cpa16(bs_a + so + s * 16, Bsrc + tt * 32 + s * 4);
        }
    };
    issue(0); CP_COMMIT();

    for (int tt = 0; tt < 36; tt++) {
        CP_WAIT0(); __syncthreads();
        if (tt < 35) { issue(tt + 1); CP_COMMIT(); }
        const float* Ap = As + (tt & 1) * 5120;
        const float* Bp = Bs + (tt & 1) * 5120;
        #pragma unroll
        for (int ks = 0; ks < 32; ks += 8) {
            unsigned a0[4], a1[4], a2[4], a3[4];
            #pragma unroll
            for (int mt = 0; mt < 4; mt++) {
                const float* q0 = Ap + (wm * 64 + mt * 16 + r) * 40 + ks + 2 * c;
                float2 la = *(const float2*)q0;
                float2 lb = *(const float2*)(q0 + 8 * 40);
                a0[mt] = F2U(la.x); a1[mt] = F2U(lb.x);
                a2[mt] = F2U(la.y); a3[mt] = F2U(lb.y);
            }
            #pragma unroll
            for (int nt = 0; nt < 4; nt++) {
                float2 bb = *(const float2*)(Bp + (wn * 32 + nt * 8 + r) * 40 + ks + 2 * c);
                unsigned b0 = F2U(bb.x), b1 = F2U(bb.y);
                #pragma unroll
                for (int mt = 0; mt < 4; mt++)
                    mma_tf32(acc[mt][nt], a0[mt], a1[mt], a2[mt], a3[mt], b0, b1);
            }
        }
    }

    const int part = (blockIdx.x * 128) / C_;     // 1152 = 9*128: no crossing
    const float sc = (part == 0) ? SCALE_ : 1.0f;
    #pragma unroll
    for (int mt = 0; mt < 4; mt++) {
        int m0 = blockIdx.y * 128 + wm * 64 + mt * 16 + r;
        int np2[2], bb2[2];
        #pragma unroll
        for (int eh = 0; eh < 2; eh++) {
            int m = m0 + eh * 8;
            bb2[eh] = m >> 11;
            np2[eh] = g_cpos[bb2[eh] * N_ + (m & (N_ - 1))];   // compacted pos
        }
        #pragma unroll
        for (int nt = 0; nt < 4; nt++) {
            int col0 = blockIdx.x * 128 - part * C_ + wn * 32 + nt * 8 + c * 2;
            float v[4] = {acc[mt][nt].x, acc[mt][nt].y, acc[mt][nt].z, acc[mt][nt].w};
            #pragma unroll
            for (int e = 0; e < 4; e++) {
                int eh = e >> 1;
                int jj = col0 + (e & 1);
                int hh = jj / HD_, dd = jj - hh * HD_;
                int bb = bb2[eh], np = np2[eh];
                float val = tf32r(v[e] * sc);
                if (part == 0)
                    g_q[((size_t)(bb * H_ + hh) * N_ + np) * HD2_ + dd] = val;
                else if (part == 1)
                    g_k[((size_t)(bb * H_ + hh) * N_ + np) * HD2_ + dd] = val;
                else
                    g_vt[((size_t)(bb * H_ + hh) * HD_ + dd) * N_ + np] = val;
            }
        }
    }
}

// ---- Kernel D: vmean[b][h*72+d] = mean over all keys of V ----
__global__ void vmean_kernel() {
    const int w = threadIdx.x >> 5, lane = threadIdx.x & 31;
    const int i = blockIdx.x * 8 + w;          // i in [0, 2304)
    const float* src = g_vt + (size_t)i * N_;
    float s = 0.f;
    for (int j = lane * 4; j < N_; j += 128) {
        float4 v = *(const float4*)(src + j);
        s += v.x + v.y + v.z + v.w;
    }
    #pragma unroll
    for (int o = 16; o > 0; o >>= 1) s += __shfl_xor_sync(0xffffffffu, s, o);
    if (lane == 0) g_vmean[i] = s * (1.0f / 2048.0f);
}

// ---- Kernel E: masked-query rows of g_ao = vmean (exact uniform softmax) ----
__global__ void maskfill_kernel(const int* __restrict__ mask) {
    const int n = blockIdx.x, b = blockIdx.y, t = threadIdx.x;   // 288 threads
    if (mask[b * N_ + n]) return;
    float4 v = *(const float4*)(g_vmean + b * C_ + t * 4);
    *(float4*)(g_ao + ((size_t)b * N_ + n) * C_ + t * 4) = v;
}

// ---- Kernel F: compacted flash attention. 128 q rows/CTA, 4 warps of 32
// rows. Single-buffered K/V (2 CTAs/SM hide load latency). Dynamic key-tile
// count ceil(cnt/64); tail keys killed by cnt-bound bias. Smem 76,032 B. ----
__global__ __launch_bounds__(128, 2) void attn_kernel() {
    extern __shared__ float smg[];
    float* Qs = smg;                 // [128][72]
    float* Ks = smg + 128 * 72;      // [64][72]
    float* Vt = Ks + 64 * 72;        // [72][72] (cols 0..63 = keys)

    const int t = threadIdx.x, l = t & 31, wid = t >> 5;
    const int r = l >> 2, c = l & 3;
    const int qt = blockIdx.x, h = blockIdx.y, b = blockIdx.z;
    const int bh = b * H_ + h;
    const int cnt = g_cnt[b];
    const int qbase = qt * 128;
    if (qbase >= cnt) return;

    const float* qp  = g_q  + ((size_t)bh * N_ + qbase) * HD2_;
    const float* kp  = g_k  + (size_t)bh * N_ * HD2_;
    const float* vtp = g_vt + (size_t)bh * HD_ * N_;
    uint32_t ks_a, vt_a;
    asm("{ .reg .u64 x; cvta.to.shared.u64 x, %1; cvt.u32.u64 %0, x; }" : "=r"(ks_a) : "l"(Ks));
    asm("{ .reg .u64 x; cvta.to.shared.u64 x, %1; cvt.u32.u64 %0, x; }" : "=r"(vt_a) : "l"(Vt));

    for (int i = t; i < 128 * 18; i += 128) {
        int row = i / 18, s = i - row * 18;
        *(float4*)&Qs[row * 72 + s * 4] = *(const float4*)(qp + (size_t)row * HD2_ + s * 4);
    }

    float4 O[2][9];
    #pragma unroll
    for (int mt = 0; mt < 2; mt++)
        #pragma unroll
        for (int nt = 0; nt < 9; nt++) O[mt][nt] = make_float4(0.f, 0.f, 0.f, 0.f);
    float mrun[4] = {-3.0e38f, -3.0e38f, -3.0e38f, -3.0e38f};
    float lrun[4] = {0.f, 0.f, 0.f, 0.f};

    const float* qb0 = Qs + (wid * 32 + r) * 72 + 2 * c;
    const int ktiles = (cnt + 63) >> 6;
    const int krow = t >> 1, kc0 = (t & 1) * 9;

    for (int kt = 0; kt < ktiles; kt++) {
        __syncthreads();                         // prev tile reads complete
        {
            const float* ksrc = kp + (size_t)(kt * 64 + krow) * HD2_;
            uint32_t kd = ks_a + (krow * 72) * 4;
            #pragma unroll
            for (int i = 0; i < 9; i++)
                cpa16(kd + (kc0 + i) * 16, ksrc + (kc0 + i) * 4);
            #pragma unroll
            for (int i = 0; i < 9; i++) {
                int idx = t + i * 128;
                int vrow = idx >> 4, vs = idx & 15;
                cpa16(vt_a + (vrow * 72 + vs * 4) * 4,
                      vtp + (size_t)vrow * N_ + kt * 64 + vs * 4);
            }
        }
        CP_COMMIT(); CP_WAIT0();
        __syncthreads();                         // tile ready

        // ---- S = Q K^T ----
        float4 S4[2][8];
        #pragma unroll
        for (int mt = 0; mt < 2; mt++)
            #pragma unroll
            for (int nt = 0; nt < 8; nt++) S4[mt][nt] = make_float4(0.f, 0.f, 0.f, 0.f);
        #pragma unroll
        for (int ks = 0; ks < 9; ks++) {
            const int kb = ks * 8;
            unsigned a0[2], a1[2], a2[2], a3[2];
            #pragma unroll
            for (int mt = 0; mt < 2; mt++) {
                float2 la = *(const float2*)(qb0 + mt * 16 * 72 + kb);
                float2 lb = *(const float2*)(qb0 + (mt * 16 + 8) * 72 + kb);
                a0[mt] = F2U(la.x); a1[mt] = F2U(lb.x);
                a2[mt] = F2U(la.y); a3[mt] = F2U(lb.y);
            }
            #pragma unroll
            for (int nt = 0; nt < 8; nt++) {
                float2 bb = *(const float2*)(Ks + (nt * 8 + r) * 72 + kb + 2 * c);
                unsigned b0 = F2U(bb.x), b1 = F2U(bb.y);
                #pragma unroll
                for (int mt = 0; mt < 2; mt++)
                    mma_tf32(S4[mt][nt], a0[mt], a1[mt], a2[mt], a3[mt], b0, b1);
            }
        }

        // ---- tail-key bias (only last tile can have invalid cols) ----
        if (kt * 64 + 64 > cnt) {
            #pragma unroll
            for (int nt = 0; nt < 8; nt++) {
                int j0 = kt * 64 + nt * 8 + 2 * c;
                float b0 = (j0 < cnt) ? 0.f : NEG_;
                float b1 = (j0 + 1 < cnt) ? 0.f : NEG_;
                #pragma unroll
                for (int mt = 0; mt < 2; mt++) {
                    S4[mt][nt].x += b0; S4[mt][nt].y += b1;
                    S4[mt][nt].z += b0; S4[mt][nt].w += b1;
                }
            }
        }

        // ---- warp-local softmax ----
        float al[4];
        #pragma unroll
        for (int mt = 0; mt < 2; mt++) {
            float pm0 = -3.0e38f, pm1 = -3.0e38f;
            #pragma unroll
            for (int nt = 0; nt < 8; nt++) {
                pm0 = fmaxf(pm0, fmaxf(S4[mt][nt].x, S4[mt][nt].y));
                pm1 = fmaxf(pm1, fmaxf(S4[mt][nt].z, S4[mt][nt].w));
            }
            pm0 = fmaxf(pm0, __shfl_xor_sync(0xffffffffu, pm0, 1));
            pm0 = fmaxf(pm0, __shfl_xor_sync(0xffffffffu, pm0, 2));
            pm1 = fmaxf(pm1, __shfl_xor_sync(0xffffffffu, pm1, 1));
            pm1 = fmaxf(pm1, __shfl_xor_sync(0xffffffffu, pm1, 2));
            float nm0 = fmaxf(mrun[mt * 2], pm0);
            float nm1 = fmaxf(mrun[mt * 2 + 1], pm1);
            float a0 = __expf(mrun[mt * 2] - nm0);
            float a1 = __expf(mrun[mt * 2 + 1] - nm1);
            float ps0 = 0.f, ps1 = 0.f;
            #pragma unroll
            for (int nt = 0; nt < 8; nt++) {
                float4& s = S4[mt][nt];
                float px = tf32r(__expf(s.x - nm0));
                float py = tf32r(__expf(s.y - nm0));
                float pz = tf32r(__expf(s.z - nm1));
                float pw = tf32r(__expf(s.w - nm1));
                s = make_float4(px, py, pz, pw);
                ps0 += px + py; ps1 += pz + pw;
            }
            ps0 += __shfl_xor_sync(0xffffffffu, ps0, 1);
            ps0 += __shfl_xor_sync(0xffffffffu, ps0, 2);
            ps1 += __shfl_xor_sync(0xffffffffu, ps1, 1);
            ps1 += __shfl_xor_sync(0xffffffffu, ps1, 2);
            lrun[mt * 2]     = lrun[mt * 2] * a0 + ps0;
            lrun[mt * 2 + 1] = lrun[mt * 2 + 1] * a1 + ps1;
            mrun[mt * 2]     = nm0;
            mrun[mt * 2 + 1] = nm1;
            al[mt * 2] = a0; al[mt * 2 + 1] = a1;
        }

        // ---- O = O*alpha + P @ V (P from accumulators) ----
        #pragma unroll
        for (int mt = 0; mt < 2; mt++)
            #pragma unroll
            for (int nt = 0; nt < 9; nt++) {
                O[mt][nt].x *= al[mt * 2];     O[mt][nt].y *= al[mt * 2];
                O[mt][nt].z *= al[mt * 2 + 1]; O[mt][nt].w *= al[mt * 2 + 1];
            }
        #pragma unroll
        for (int kk = 0; kk < 8; kk++) {
            unsigned pa0[2], pa1[2], pa2[2], pa3[2];
            #pragma unroll
            for (int mt = 0; mt < 2; mt++) {
                pa0[mt] = F2U(S4[mt][kk].x); pa1[mt] = F2U(S4[mt][kk].z);
                pa2[mt] = F2U(S4[mt][kk].y); pa3[mt] = F2U(S4[mt][kk].w);
            }
            const int kb2 = kk * 8 + 2 * c;
            #pragma unroll
            for (int nt = 0; nt < 9; nt++) {
                float2 bb = *(const float2*)(Vt + (nt * 8 + r) * 72 + kb2);
                unsigned b0 = F2U(bb.x), b1 = F2U(bb.y);
                #pragma unroll
                for (int mt = 0; mt < 2; mt++)
                    mma_tf32(O[mt][nt], pa0[mt], pa1[mt], pa2[mt], pa3[mt], b0, b1);
            }
        }
    }

    // ---- epilogue: /l, scatter to ORIGINAL row order via cidx ----
    #pragma unroll
    for (int mt = 0; mt < 2; mt++) {
        float inv0 = 1.0f / lrun[mt * 2];
        float inv1 = 1.0f / lrun[mt * 2 + 1];
        int j0 = qbase + wid * 32 + mt * 16 + r;
        int j1 = j0 + 8;
        if (j0 < cnt) {
            int n0 = g_cidx[b * N_ + j0];
            float* op = g_ao + ((size_t)b * N_ + n0) * C_ + h * HD_;
            #pragma unroll
            for (int nt = 0; nt < 9; nt++) {
                int d0 = nt * 8 + 2 * c;
                *(float2*)(op + d0) = make_float2(tf32r(O[mt][nt].x * inv0),
                                                  tf32r(O[mt][nt].y * inv0));
            }
        }
        if (j1 < cnt) {
            int n1 = g_cidx[b * N_ + j1];
            float* op = g_ao + ((size_t)b * N_ + n1) * C_ + h * HD_;
            #pragma unroll
            for (int nt = 0; nt < 9; nt++) {
                int d0 = nt * 8 + 2 * c;
                *(float2*)(op + d0) = make_float2(tf32r(O[mt][nt].z * inv1),
                                                  tf32r(O[mt][nt].w * inv1));
            }
        }
    }
}

// ---- Kernel G: proj GEMM (R13, unchanged) ----
__global__ __launch_bounds__(256, 2) void proj_kernel(const float* __restrict__ wr,
                                                      const float* __restrict__ bias,
                                                      float* __restrict__ out) {
    extern __shared__ float smg[];
    float* As = smg;
    float* Bs = smg + 2 * 128 * 40;
    const int t = threadIdx.x, l = t & 31, wid = t >> 5;
    const int wm = wid >> 2, wn = wid & 3;
    const int r = l >> 2, c = l & 3;
    const int lrow = t >> 1, lseg = t & 1;
    const float* Asrc = g_ao + ((size_t)blockIdx.y * 128 + lrow) * C_;
    const float* Bsrc = wr   + ((size_t)blockIdx.x * 128 + lrow) * C_;
    const uint32_t as_a = (uint32_t)__cvta_generic_to_shared(As) + lrow * 40 * 4;
    const uint32_t bs_a = (uint32_t)__cvta_generic_to_shared(Bs) + lrow * 40 * 4;

    float4 acc[4][4];
    #pragma unroll
    for (int i = 0; i < 4; i++)
        #pragma unroll
        for (int j = 0; j < 4; j++) acc[i][j] = make_float4(0.f, 0.f, 0.f, 0.f);

    auto issue = [&](int tt) {
        const int so = (tt & 1) * 5120 * 4;
        #pragma unroll
        for (int k2 = 0; k2 < 4; k2++) {
            int s = lseg + 2 * k2;
            cpa16(as_a + so + s * 16, Asrc + tt * 32 + s * 4);
            cpa16(bs_a + so + s * 16, Bsrc + tt * 32 + s * 4);
        }
    };
    issue(0); CP_COMMIT();

    for (int tt = 0; tt < 36; tt++) {
        CP_WAIT0(); __syncthreads();
        if (tt < 35) { issue(tt + 1); CP_COMMIT(); }
        const float* Ap = As + (tt & 1) * 5120;
        const float* Bp = Bs + (tt & 1) * 5120;
        #pragma unroll
        for (int ks = 0; ks < 32; ks += 8) {
            unsigned a0[4], a1[4], a2[4], a3[4];
            #pragma unroll
            for (int mt = 0; mt < 4; mt++) {
                const float* q0 = Ap + (wm * 64 + mt * 16 + r) * 40 + ks + 2 * c;
                float2 la = *(const float2*)q0;
                float2 lb = *(const float2*)(q0 + 8 * 40);
                a0[mt] = F2U(la.x); a1[mt] = F2U(lb.x);
                a2[mt] = F2U(la.y); a3[mt] = F2U(lb.y);
            }
            #pragma unroll
            for (int nt = 0; nt < 4; nt++) {
                float2 bb = *(const float2*)(Bp + (wn * 32 + nt * 8 + r) * 40 + ks + 2 * c);
                unsigned b0 = F2U(bb.x), b1 = F2U(bb.y);
                #pragma unroll
                for (int mt = 0; mt < 4; mt++)
                    mma_tf32(acc[mt][nt], a0[mt], a1[mt], a2[mt], a3[mt], b0, b1);
            }
        }
    }

    #pragma unroll
    for (int mt = 0; mt < 4; mt++) {
        int m0 = blockIdx.y * 128 + wm * 64 + mt * 16 + r;
        #pragma unroll
        for (int nt = 0; nt < 4; nt++) {
            int col0 = blockIdx.x * 128 + wn * 32 + nt * 8 + c * 2;
            float bv0 = bias[col0], bv1 = bias[col0 + 1];
            out[(size_t)m0 * C_ + col0]           = acc[mt][nt].x + bv0;
            out[(size_t)m0 * C_ + col0 + 1]       = acc[mt][nt].y + bv1;
            out[(size_t)(m0 + 8) * C_ + col0]     = acc[mt][nt].z + bv0;
            out[(size_t)(m0 + 8) * C_ + col0 + 1] = acc[mt][nt].w + bv1;
        }
    }
}

// ---------------------------------------------------------------------------
extern "C" void kernel_launch(void* const* d_in, const int* in_sizes, int n_in,
                              void* d_out, int out_size) {
    const float* x      = (const float*)d_in[0];
    const int*   amask  = (const int*)  d_in[1];
    const float* w_qkv  = (const float*)d_in[2];
    const float* w_proj = (const float*)d_in[3];
    const float* b_proj = (const float*)d_in[4];
    float* out = (float*)d_out;

    const int gemm_smem = 2 * (2 * 128 * 40) * 4;            // 81,920 B
    const int attn_smem = (128*72 + 64*72 + 72*72) * 4;      // 76,032 B
    cudaFuncSetAttribute(qkv_kernel,  cudaFuncAttributeMaxDynamicSharedMemorySize, gemm_smem);
    cudaFuncSetAttribute(proj_kernel, cudaFuncAttributeMaxDynamicSharedMemorySize, gemm_smem);
    cudaFuncSetAttribute(attn_kernel, cudaFuncAttributeMaxDynamicSharedMemorySize, attn_smem);

    float* xr; float* wq; float* wp;
    cudaGetSymbolAddress((void**)&xr, g_xr);
    cudaGetSymbolAddress((void**)&wq, g_wq);
    cudaGetSymbolAddress((void**)&wp, g_wp);

    const int n4x = B_*N_*C_/4, n4q = 3*C_*C_/4, n4p = C_*C_/4;
    compact_kernel<<<B_, 256>>>(amask);
    round_kernel<<<(n4x + 255)/256, 256>>>((const float4*)x,      (float4*)xr, n4x);
    round_kernel<<<(n4q + 255)/256, 256>>>((const float4*)w_qkv,  (float4*)wq, n4q);
    round_kernel<<<(n4p + 255)/256, 256>>>((const float4*)w_proj, (float4*)wp, n4p);

    qkv_kernel <<<dim3(27, 32), 256, gemm_smem>>>(xr, wq);
    vmean_kernel<<<288, 256>>>();
    maskfill_kernel<<<dim3(N_, B_), 288>>>(amask);
    attn_kernel<<<dim3(9, 16, 2), 128, attn_smem>>>();
    proj_kernel<<<dim3(9, 32), 256, gemm_smem>>>(wp, b_proj, out);
}